// round 1
// baseline (speedup 1.0000x reference)
#include <cuda_runtime.h>
#include <cuda_bf16.h>

#define BB   2
#define SEQ  2048
#define DIN  1024
#define DOUT 1024
#define NH   16
#define HD   64
#define MROWS (BB*SEQ)   // 4096

// Scratch (allocation-free requirement -> __device__ globals)
__device__ float g_q[BB*NH*SEQ*HD];    // [B,H,N,HD]
__device__ float g_k[BB*NH*SEQ*HD];
__device__ float g_v[BB*NH*SEQ*HD];
__device__ float g_ctx[MROWS*DOUT];    // [B*N, DOUT]

// ---------------------------------------------------------------------------
// Fused QKV projection: C = x @ W, scattered into [B,H,N,HD] layout.
// Tile 64x64x16, 256 threads, 4x4 per-thread microtile.
// grid: (DOUT/64, MROWS/64, 3)  z: 0=Q 1=K 2=V
// ---------------------------------------------------------------------------
__global__ __launch_bounds__(256) void qkv_gemm(
    const float* __restrict__ x,
    const float* __restrict__ Wq,
    const float* __restrict__ Wk,
    const float* __restrict__ Wv)
{
    __shared__ float As[16][64];
    __shared__ float Bs[16][64];

    const float* W   = (blockIdx.z == 0) ? Wq : (blockIdx.z == 1) ? Wk : Wv;
    float*       dst = (blockIdx.z == 0) ? g_q : (blockIdx.z == 1) ? g_k : g_v;

    const int t  = threadIdx.x;
    const int m0 = blockIdx.y * 64;
    const int n0 = blockIdx.x * 64;
    const int tx = t & 15;
    const int ty = t >> 4;

    // A load map: 64 rows x 16 cols, float4 per thread
    const int am = t >> 2;
    const int ak = (t & 3) * 4;

    float acc[4][4];
    #pragma unroll
    for (int i = 0; i < 4; i++)
        #pragma unroll
        for (int j = 0; j < 4; j++) acc[i][j] = 0.f;

    for (int k0 = 0; k0 < DIN; k0 += 16) {
        float4 av = *(const float4*)&x[(m0 + am) * DIN + k0 + ak];
        As[ak + 0][am] = av.x;
        As[ak + 1][am] = av.y;
        As[ak + 2][am] = av.z;
        As[ak + 3][am] = av.w;
        float4 bv = *(const float4*)&W[(k0 + ty) * DOUT + n0 + tx * 4];
        *(float4*)&Bs[ty][tx * 4] = bv;
        __syncthreads();

        #pragma unroll
        for (int kk = 0; kk < 16; kk++) {
            float4 a4 = *(const float4*)&As[kk][ty * 4];
            float4 b4 = *(const float4*)&Bs[kk][tx * 4];
            float a[4] = {a4.x, a4.y, a4.z, a4.w};
            float b[4] = {b4.x, b4.y, b4.z, b4.w};
            #pragma unroll
            for (int i = 0; i < 4; i++)
                #pragma unroll
                for (int j = 0; j < 4; j++)
                    acc[i][j] = fmaf(a[i], b[j], acc[i][j]);
        }
        __syncthreads();
    }

    // Epilogue: scatter to [B,H,N,HD]. BN=64 == HD -> whole block is one head.
    const int h = n0 >> 6;
    #pragma unroll
    for (int i = 0; i < 4; i++) {
        int m = m0 + ty * 4 + i;
        int b = m >> 11;          // /2048
        int n = m & 2047;
        float4 v = make_float4(acc[i][0], acc[i][1], acc[i][2], acc[i][3]);
        *(float4*)&dst[(((b << 4) + h) * SEQ + n) * HD + tx * 4] = v;
    }
}

// ---------------------------------------------------------------------------
// Causal flash attention. One thread per query row (q + acc in registers),
// K/V chunks of 64 keys staged in smem, broadcast float4 reads.
// grid: (SEQ/128, BB*NH), block 128.
// ---------------------------------------------------------------------------
__global__ __launch_bounds__(128) void attn_kernel()
{
    __shared__ float Ks[64][64];
    __shared__ float Vs[64][64];

    // Reverse tile order so heavy (long-causal-span) blocks launch first.
    const int tile = (gridDim.x - 1) - blockIdx.x;
    const int bh   = blockIdx.y;
    const int qi   = tile * 128 + threadIdx.x;

    const float* qp = &g_q[(bh * SEQ + qi) * HD];
    float q[64];
    #pragma unroll
    for (int d4 = 0; d4 < 16; d4++) {
        float4 v = *(const float4*)&qp[d4 * 4];
        q[d4 * 4 + 0] = v.x; q[d4 * 4 + 1] = v.y;
        q[d4 * 4 + 2] = v.z; q[d4 * 4 + 3] = v.w;
    }

    float acc[64];
    #pragma unroll
    for (int d = 0; d < 64; d++) acc[d] = 0.f;
    float m = -1e30f, l = 0.f;

    const int kend = tile * 128 + 128;   // exclusive bound on keys this tile needs
    for (int kb = 0; kb < kend; kb += 64) {
        // Cooperative K/V chunk load: 64x64 floats each, fully coalesced
        const float* kp = &g_k[(bh * SEQ + kb) * HD];
        const float* vp = &g_v[(bh * SEQ + kb) * HD];
        #pragma unroll
        for (int r = 0; r < 8; r++) {
            int idx = r * 512 + threadIdx.x * 4;
            *(float4*)&Ks[0][idx] = *(const float4*)&kp[idx];
            *(float4*)&Vs[0][idx] = *(const float4*)&vp[idx];
        }
        __syncthreads();

        #pragma unroll
        for (int j0 = 0; j0 < 64; j0 += 32) {
            float s[32];
            #pragma unroll
            for (int jj = 0; jj < 32; jj++) {
                const float* kr = &Ks[j0 + jj][0];
                float sv = 0.f;
                #pragma unroll
                for (int d4 = 0; d4 < 16; d4++) {
                    float4 kv = *(const float4*)&kr[d4 * 4];
                    sv = fmaf(q[d4 * 4 + 0], kv.x, sv);
                    sv = fmaf(q[d4 * 4 + 1], kv.y, sv);
                    sv = fmaf(q[d4 * 4 + 2], kv.z, sv);
                    sv = fmaf(q[d4 * 4 + 3], kv.w, sv);
                }
                int kj = kb + j0 + jj;
                s[jj] = (kj <= qi) ? sv * 0.125f : -1e30f;   // 1/sqrt(64)
            }
            float cmax = s[0];
            #pragma unroll
            for (int jj = 1; jj < 32; jj++) cmax = fmaxf(cmax, s[jj]);
            float mnew  = fmaxf(m, cmax);
            float scale = __expf(m - mnew);
            l *= scale;
            #pragma unroll
            for (int d = 0; d < 64; d++) acc[d] *= scale;
            #pragma unroll
            for (int jj = 0; jj < 32; jj++) {
                float p = __expf(s[jj] - mnew);
                l += p;
                const float* vr = &Vs[j0 + jj][0];
                #pragma unroll
                for (int d4 = 0; d4 < 16; d4++) {
                    float4 vv = *(const float4*)&vr[d4 * 4];
                    acc[d4 * 4 + 0] = fmaf(p, vv.x, acc[d4 * 4 + 0]);
                    acc[d4 * 4 + 1] = fmaf(p, vv.y, acc[d4 * 4 + 1]);
                    acc[d4 * 4 + 2] = fmaf(p, vv.z, acc[d4 * 4 + 2]);
                    acc[d4 * 4 + 3] = fmaf(p, vv.w, acc[d4 * 4 + 3]);
                }
            }
            m = mnew;
        }
        __syncthreads();
    }

    const float inv = 1.f / l;
    const int b = bh >> 4, h = bh & 15;
    float* op = &g_ctx[(b * SEQ + qi) * DOUT + h * HD];
    #pragma unroll
    for (int d4 = 0; d4 < 16; d4++) {
        float4 v = make_float4(acc[d4 * 4 + 0] * inv, acc[d4 * 4 + 1] * inv,
                               acc[d4 * 4 + 2] * inv, acc[d4 * 4 + 3] * inv);
        *(float4*)&op[d4 * 4] = v;
    }
}

// ---------------------------------------------------------------------------
// Output projection: out = ctx @ Wo + bo. Same SGEMM tiling.
// grid: (DOUT/64, MROWS/64)
// ---------------------------------------------------------------------------
__global__ __launch_bounds__(256) void proj_gemm(
    const float* __restrict__ Wo,
    const float* __restrict__ bo,
    float* __restrict__ out)
{
    __shared__ float As[16][64];
    __shared__ float Bs[16][64];

    const int t  = threadIdx.x;
    const int m0 = blockIdx.y * 64;
    const int n0 = blockIdx.x * 64;
    const int tx = t & 15;
    const int ty = t >> 4;
    const int am = t >> 2;
    const int ak = (t & 3) * 4;

    float acc[4][4];
    #pragma unroll
    for (int i = 0; i < 4; i++)
        #pragma unroll
        for (int j = 0; j < 4; j++) acc[i][j] = 0.f;

    for (int k0 = 0; k0 < DOUT; k0 += 16) {
        float4 av = *(const float4*)&g_ctx[(m0 + am) * DOUT + k0 + ak];
        As[ak + 0][am] = av.x;
        As[ak + 1][am] = av.y;
        As[ak + 2][am] = av.z;
        As[ak + 3][am] = av.w;
        float4 bv = *(const float4*)&Wo[(k0 + ty) * DOUT + n0 + tx * 4];
        *(float4*)&Bs[ty][tx * 4] = bv;
        __syncthreads();

        #pragma unroll
        for (int kk = 0; kk < 16; kk++) {
            float4 a4 = *(const float4*)&As[kk][ty * 4];
            float4 b4 = *(const float4*)&Bs[kk][tx * 4];
            float a[4] = {a4.x, a4.y, a4.z, a4.w};
            float b[4] = {b4.x, b4.y, b4.z, b4.w};
            #pragma unroll
            for (int i = 0; i < 4; i++)
                #pragma unroll
                for (int j = 0; j < 4; j++)
                    acc[i][j] = fmaf(a[i], b[j], acc[i][j]);
        }
        __syncthreads();
    }

    float4 bias = *(const float4*)&bo[n0 + tx * 4];
    #pragma unroll
    for (int i = 0; i < 4; i++) {
        int m = m0 + ty * 4 + i;
        float4 v = make_float4(acc[i][0] + bias.x, acc[i][1] + bias.y,
                               acc[i][2] + bias.z, acc[i][3] + bias.w);
        *(float4*)&out[m * DOUT + n0 + tx * 4] = v;
    }
}

// ---------------------------------------------------------------------------
extern "C" void kernel_launch(void* const* d_in, const int* in_sizes, int n_in,
                              void* d_out, int out_size)
{
    const float* x  = (const float*)d_in[0];
    const float* Wq = (const float*)d_in[1];
    const float* Wk = (const float*)d_in[2];
    const float* Wv = (const float*)d_in[3];
    const float* Wo = (const float*)d_in[4];
    const float* bo = (const float*)d_in[5];
    float* out = (float*)d_out;

    dim3 gQKV(DOUT / 64, MROWS / 64, 3);
    qkv_gemm<<<gQKV, 256>>>(x, Wq, Wk, Wv);

    dim3 gAtt(SEQ / 128, BB * NH);
    attn_kernel<<<gAtt, 128>>>();

    dim3 gPrj(DOUT / 64, MROWS / 64);
    proj_gemm<<<gPrj, 256>>>(Wo, bo, out);
}

// round 2
// speedup vs baseline: 1.9233x; 1.9233x over previous
#include <cuda_runtime.h>
#include <cuda_bf16.h>

#define BB   2
#define SEQ  2048
#define DIN  1024
#define DOUT 1024
#define NH   16
#define HD   64
#define MROWS (BB*SEQ)   // 4096

// Scratch (allocation-free requirement -> __device__ globals)
__device__ float g_q[BB*NH*SEQ*HD];    // [B,H,N,HD]
__device__ float g_k[BB*NH*SEQ*HD];
__device__ float g_v[BB*NH*SEQ*HD];
__device__ float g_ctx[MROWS*DOUT];    // [B*N, DOUT]

// ---------------------------------------------------------------------------
// 128x128x16 SGEMM, 256 threads, 8x8 microtile, register prefetch pipeline.
// qkv variant: z selects Wq/Wk/Wv; epilogue scatters into [B,H,N,HD].
// ---------------------------------------------------------------------------
__global__ __launch_bounds__(256, 2) void qkv_gemm(
    const float* __restrict__ x,
    const float* __restrict__ Wq,
    const float* __restrict__ Wk,
    const float* __restrict__ Wv)
{
    __shared__ float As[16][132];   // A transposed: As[k][m]
    __shared__ float Bs[16][128];   // B natural:    Bs[k][n]

    const float* W   = (blockIdx.z == 0) ? Wq : (blockIdx.z == 1) ? Wk : Wv;
    float*       dst = (blockIdx.z == 0) ? g_q : (blockIdx.z == 1) ? g_k : g_v;

    const int t  = threadIdx.x;
    const int tx = t & 15, ty = t >> 4;
    const int m0 = blockIdx.y * 128, n0 = blockIdx.x * 128;
    const int am = t >> 2, ak = (t & 3) * 4;
    const int brow = t >> 5, bcol = (t & 31) * 4;

    const float* Ap0 = x + (m0 + am) * DIN + ak;
    const float* Ap1 = Ap0 + 64 * DIN;
    const float* Bp0 = W + brow * DOUT + n0 + bcol;
    const float* Bp1 = Bp0 + 8 * DOUT;

    float acc[8][8];
    #pragma unroll
    for (int i = 0; i < 8; i++)
        #pragma unroll
        for (int j = 0; j < 8; j++) acc[i][j] = 0.f;

    float4 pa0 = *(const float4*)Ap0;
    float4 pa1 = *(const float4*)Ap1;
    float4 pb0 = *(const float4*)Bp0;
    float4 pb1 = *(const float4*)Bp1;

    int k0 = 0;
    for (;;) {
        As[ak+0][am] = pa0.x; As[ak+1][am] = pa0.y;
        As[ak+2][am] = pa0.z; As[ak+3][am] = pa0.w;
        As[ak+0][am+64] = pa1.x; As[ak+1][am+64] = pa1.y;
        As[ak+2][am+64] = pa1.z; As[ak+3][am+64] = pa1.w;
        *(float4*)&Bs[brow][bcol]     = pb0;
        *(float4*)&Bs[brow + 8][bcol] = pb1;
        __syncthreads();

        k0 += 16;
        const bool more = (k0 < DIN);
        if (more) {
            pa0 = *(const float4*)(Ap0 + k0);
            pa1 = *(const float4*)(Ap1 + k0);
            pb0 = *(const float4*)(Bp0 + (size_t)k0 * DOUT);
            pb1 = *(const float4*)(Bp1 + (size_t)k0 * DOUT);
        }

        #pragma unroll
        for (int kk = 0; kk < 16; kk++) {
            float a[8], b[8];
            *(float4*)(a)     = *(const float4*)&As[kk][ty * 4];
            *(float4*)(a + 4) = *(const float4*)&As[kk][64 + ty * 4];
            *(float4*)(b)     = *(const float4*)&Bs[kk][tx * 4];
            *(float4*)(b + 4) = *(const float4*)&Bs[kk][64 + tx * 4];
            #pragma unroll
            for (int i = 0; i < 8; i++)
                #pragma unroll
                for (int j = 0; j < 8; j++)
                    acc[i][j] = fmaf(a[i], b[j], acc[i][j]);
        }
        if (!more) break;
        __syncthreads();
    }

    // scatter epilogue into [B,H,N,HD]; N-tile of 128 spans 2 heads
    const int h0 = n0 >> 6;
    #pragma unroll
    for (int rg = 0; rg < 2; rg++)
        #pragma unroll
        for (int i = 0; i < 4; i++) {
            int m = m0 + rg * 64 + ty * 4 + i;
            int b = m >> 11, n = m & 2047;
            #pragma unroll
            for (int cg = 0; cg < 2; cg++) {
                int h = h0 + cg;
                float4 v = make_float4(acc[rg*4+i][cg*4+0], acc[rg*4+i][cg*4+1],
                                       acc[rg*4+i][cg*4+2], acc[rg*4+i][cg*4+3]);
                *(float4*)&dst[(((b << 4) + h) * SEQ + n) * HD + tx * 4] = v;
            }
        }
}

// ---------------------------------------------------------------------------
// Output projection: out = ctx @ Wo + bo. Same 128x128x16 tiling.
// ---------------------------------------------------------------------------
__global__ __launch_bounds__(256, 2) void proj_gemm(
    const float* __restrict__ Wo,
    const float* __restrict__ bo,
    float* __restrict__ out)
{
    __shared__ float As[16][132];
    __shared__ float Bs[16][128];

    const int t  = threadIdx.x;
    const int tx = t & 15, ty = t >> 4;
    const int m0 = blockIdx.y * 128, n0 = blockIdx.x * 128;
    const int am = t >> 2, ak = (t & 3) * 4;
    const int brow = t >> 5, bcol = (t & 31) * 4;

    const float* Ap0 = g_ctx + (m0 + am) * DOUT + ak;
    const float* Ap1 = Ap0 + 64 * DOUT;
    const float* Bp0 = Wo + brow * DOUT + n0 + bcol;
    const float* Bp1 = Bp0 + 8 * DOUT;

    float acc[8][8];
    #pragma unroll
    for (int i = 0; i < 8; i++)
        #pragma unroll
        for (int j = 0; j < 8; j++) acc[i][j] = 0.f;

    float4 pa0 = *(const float4*)Ap0;
    float4 pa1 = *(const float4*)Ap1;
    float4 pb0 = *(const float4*)Bp0;
    float4 pb1 = *(const float4*)Bp1;

    int k0 = 0;
    for (;;) {
        As[ak+0][am] = pa0.x; As[ak+1][am] = pa0.y;
        As[ak+2][am] = pa0.z; As[ak+3][am] = pa0.w;
        As[ak+0][am+64] = pa1.x; As[ak+1][am+64] = pa1.y;
        As[ak+2][am+64] = pa1.z; As[ak+3][am+64] = pa1.w;
        *(float4*)&Bs[brow][bcol]     = pb0;
        *(float4*)&Bs[brow + 8][bcol] = pb1;
        __syncthreads();

        k0 += 16;
        const bool more = (k0 < DOUT);
        if (more) {
            pa0 = *(const float4*)(Ap0 + k0);
            pa1 = *(const float4*)(Ap1 + k0);
            pb0 = *(const float4*)(Bp0 + (size_t)k0 * DOUT);
            pb1 = *(const float4*)(Bp1 + (size_t)k0 * DOUT);
        }

        #pragma unroll
        for (int kk = 0; kk < 16; kk++) {
            float a[8], b[8];
            *(float4*)(a)     = *(const float4*)&As[kk][ty * 4];
            *(float4*)(a + 4) = *(const float4*)&As[kk][64 + ty * 4];
            *(float4*)(b)     = *(const float4*)&Bs[kk][tx * 4];
            *(float4*)(b + 4) = *(const float4*)&Bs[kk][64 + tx * 4];
            #pragma unroll
            for (int i = 0; i < 8; i++)
                #pragma unroll
                for (int j = 0; j < 8; j++)
                    acc[i][j] = fmaf(a[i], b[j], acc[i][j]);
        }
        if (!more) break;
        __syncthreads();
    }

    float4 bias0 = *(const float4*)&bo[n0 + tx * 4];
    float4 bias1 = *(const float4*)&bo[n0 + 64 + tx * 4];
    #pragma unroll
    for (int rg = 0; rg < 2; rg++)
        #pragma unroll
        for (int i = 0; i < 4; i++) {
            int m = m0 + rg * 64 + ty * 4 + i;
            float4 v0 = make_float4(acc[rg*4+i][0] + bias0.x, acc[rg*4+i][1] + bias0.y,
                                    acc[rg*4+i][2] + bias0.z, acc[rg*4+i][3] + bias0.w);
            float4 v1 = make_float4(acc[rg*4+i][4] + bias1.x, acc[rg*4+i][5] + bias1.y,
                                    acc[rg*4+i][6] + bias1.z, acc[rg*4+i][7] + bias1.w);
            *(float4*)&out[m * DOUT + n0 + tx * 4]      = v0;
            *(float4*)&out[m * DOUT + n0 + 64 + tx * 4] = v1;
        }
}

// ---------------------------------------------------------------------------
// Block-GEMM causal flash attention.
// Q tile 128 x 64 (transposed in smem), K tiles of 64. S via 8x4 microtile,
// half-warp shuffle softmax, P staged in smem, PV as second GEMM.
// grid: (SEQ/128, BB*NH), block 256. Dynamic smem 103424 B.
// ---------------------------------------------------------------------------
#define QPAD 132
#define KPAD 68
#define PPAD 68
#define ATTN_SMEM ((64*QPAD + 64*KPAD + 64*KPAD + 128*PPAD) * 4)

__global__ __launch_bounds__(256) void attn_kernel()
{
    extern __shared__ float smf[];
    float* Qs = smf;                   // [64][QPAD]  Qs[d][i]
    float* Ks = Qs + 64 * QPAD;        // [64][KPAD]  Ks[d][j]
    float* Vs = Ks + 64 * KPAD;        // [64][KPAD]  Vs[j][c]
    float* Ps = Vs + 64 * KPAD;        // [128][PPAD] Ps[i][j]

    const int t  = threadIdx.x;
    const int tx = t & 15, ty = t >> 4;
    const int tile = (gridDim.x - 1) - blockIdx.x;   // heavy tiles first
    const int bh   = blockIdx.y;
    const int q0   = tile * 128;

    // load Q transposed
    const float* qbase = g_q + (bh * SEQ + q0) * HD;
    #pragma unroll
    for (int i = 0; i < 8; i++) {
        int id = t + i * 256;
        int qr = id >> 4, d4 = (id & 15) * 4;
        float4 v = *(const float4*)&qbase[qr * HD + d4];
        Qs[(d4 + 0) * QPAD + qr] = v.x;
        Qs[(d4 + 1) * QPAD + qr] = v.y;
        Qs[(d4 + 2) * QPAD + qr] = v.z;
        Qs[(d4 + 3) * QPAD + qr] = v.w;
    }

    float m[8], l[8], acc[8][4];
    #pragma unroll
    for (int r = 0; r < 8; r++) {
        m[r] = -1e30f; l[r] = 0.f;
        #pragma unroll
        for (int c = 0; c < 4; c++) acc[r][c] = 0.f;
    }

    const float* kbase = g_k + bh * SEQ * HD;
    const float* vbase = g_v + bh * SEQ * HD;

    __syncthreads();

    for (int kb = 0; kb < q0 + 128; kb += 64) {
        // stage K (transposed) and V (natural)
        #pragma unroll
        for (int i = 0; i < 4; i++) {
            int id = t + i * 256;
            int kr = id >> 4, d4 = (id & 15) * 4;
            float4 kv = *(const float4*)&kbase[(kb + kr) * HD + d4];
            Ks[(d4 + 0) * KPAD + kr] = kv.x;
            Ks[(d4 + 1) * KPAD + kr] = kv.y;
            Ks[(d4 + 2) * KPAD + kr] = kv.z;
            Ks[(d4 + 3) * KPAD + kr] = kv.w;
            float4 vv = *(const float4*)&vbase[(kb + kr) * HD + d4];
            *(float4*)&Vs[kr * KPAD + d4] = vv;
        }
        __syncthreads();

        // S = Q K^T  (128 x 64)
        float s[8][4];
        #pragma unroll
        for (int r = 0; r < 8; r++)
            #pragma unroll
            for (int c = 0; c < 4; c++) s[r][c] = 0.f;

        #pragma unroll 8
        for (int d = 0; d < 64; d++) {
            float a[8], b[4];
            *(float4*)(a)     = *(const float4*)&Qs[d * QPAD + ty * 4];
            *(float4*)(a + 4) = *(const float4*)&Qs[d * QPAD + 64 + ty * 4];
            *(float4*)(b)     = *(const float4*)&Ks[d * KPAD + tx * 4];
            #pragma unroll
            for (int r = 0; r < 8; r++)
                #pragma unroll
                for (int c = 0; c < 4; c++)
                    s[r][c] = fmaf(a[r], b[c], s[r][c]);
        }

        // mask + scale (1/sqrt(64) = 0.125)
        if (kb >= q0) {
            #pragma unroll
            for (int r = 0; r < 8; r++) {
                int qi = q0 + (r >> 2) * 64 + ty * 4 + (r & 3);
                #pragma unroll
                for (int c = 0; c < 4; c++) {
                    int kj = kb + tx * 4 + c;
                    s[r][c] = (kj <= qi) ? s[r][c] * 0.125f : -1e30f;
                }
            }
        } else {
            #pragma unroll
            for (int r = 0; r < 8; r++)
                #pragma unroll
                for (int c = 0; c < 4; c++) s[r][c] *= 0.125f;
        }

        // online softmax (row reduce across the 16 lanes sharing ty)
        #pragma unroll
        for (int r = 0; r < 8; r++) {
            float mx = fmaxf(fmaxf(s[r][0], s[r][1]), fmaxf(s[r][2], s[r][3]));
            #pragma unroll
            for (int off = 1; off < 16; off <<= 1)
                mx = fmaxf(mx, __shfl_xor_sync(0xffffffffu, mx, off));
            float mn  = fmaxf(m[r], mx);
            float scl = __expf(m[r] - mn);
            m[r] = mn;
            float p0 = __expf(s[r][0] - mn);
            float p1 = __expf(s[r][1] - mn);
            float p2 = __expf(s[r][2] - mn);
            float p3 = __expf(s[r][3] - mn);
            float ls = (p0 + p1) + (p2 + p3);
            #pragma unroll
            for (int off = 1; off < 16; off <<= 1)
                ls += __shfl_xor_sync(0xffffffffu, ls, off);
            l[r] = l[r] * scl + ls;
            #pragma unroll
            for (int c = 0; c < 4; c++) acc[r][c] *= scl;
            int row = (r >> 2) * 64 + ty * 4 + (r & 3);
            *(float4*)&Ps[row * PPAD + tx * 4] = make_float4(p0, p1, p2, p3);
        }
        __syncthreads();

        // O += P @ V
        #pragma unroll 4
        for (int j0 = 0; j0 < 64; j0 += 4) {
            float4 a4[8];
            #pragma unroll
            for (int r = 0; r < 8; r++) {
                int row = (r >> 2) * 64 + ty * 4 + (r & 3);
                a4[r] = *(const float4*)&Ps[row * PPAD + j0];
            }
            #pragma unroll
            for (int jj = 0; jj < 4; jj++) {
                float4 bv = *(const float4*)&Vs[(j0 + jj) * KPAD + tx * 4];
                #pragma unroll
                for (int r = 0; r < 8; r++) {
                    float av = (jj == 0) ? a4[r].x : (jj == 1) ? a4[r].y :
                               (jj == 2) ? a4[r].z : a4[r].w;
                    acc[r][0] = fmaf(av, bv.x, acc[r][0]);
                    acc[r][1] = fmaf(av, bv.y, acc[r][1]);
                    acc[r][2] = fmaf(av, bv.z, acc[r][2]);
                    acc[r][3] = fmaf(av, bv.w, acc[r][3]);
                }
            }
        }
        __syncthreads();   // protect Ks/Vs/Ps before next tile load
    }

    const int b = bh >> 4, h = bh & 15;
    #pragma unroll
    for (int r = 0; r < 8; r++) {
        int qi = q0 + (r >> 2) * 64 + ty * 4 + (r & 3);
        float inv = 1.f / l[r];
        *(float4*)&g_ctx[(b * SEQ + qi) * DOUT + h * HD + tx * 4] =
            make_float4(acc[r][0] * inv, acc[r][1] * inv,
                        acc[r][2] * inv, acc[r][3] * inv);
    }
}

// ---------------------------------------------------------------------------
extern "C" void kernel_launch(void* const* d_in, const int* in_sizes, int n_in,
                              void* d_out, int out_size)
{
    const float* x  = (const float*)d_in[0];
    const float* Wq = (const float*)d_in[1];
    const float* Wk = (const float*)d_in[2];
    const float* Wv = (const float*)d_in[3];
    const float* Wo = (const float*)d_in[4];
    const float* bo = (const float*)d_in[5];
    float* out = (float*)d_out;

    cudaFuncSetAttribute(attn_kernel,
                         cudaFuncAttributeMaxDynamicSharedMemorySize, ATTN_SMEM);

    qkv_gemm<<<dim3(DOUT / 128, MROWS / 128, 3), 256>>>(x, Wq, Wk, Wv);
    attn_kernel<<<dim3(SEQ / 128, BB * NH), 256, ATTN_SMEM>>>();
    proj_gemm<<<dim3(DOUT / 128, MROWS / 128), 256>>>(Wo, bo, out);
}

// round 3
// speedup vs baseline: 4.4454x; 2.3114x over previous
#include <cuda_runtime.h>
#include <cuda_bf16.h>
#include <cstdint>

#define BB   2
#define SEQ  2048
#define DIN  1024
#define DOUT 1024
#define NH   16
#define HD   64
#define MROWS (BB*SEQ)   // 4096

// Scratch (allocation-free requirement -> __device__ globals)
__device__ float g_q[BB*NH*SEQ*HD];    // [B,H,N,HD]
__device__ float g_k[BB*NH*SEQ*HD];
__device__ float g_v[BB*NH*SEQ*HD];
__device__ float g_ctx[MROWS*DOUT];    // [B*N, DOUT]

// ---------------------------------------------------------------------------
// helpers
// ---------------------------------------------------------------------------
__device__ __forceinline__ uint32_t f2tf(float x) {
    uint32_t u;
    asm("cvt.rna.tf32.f32 %0, %1;" : "=r"(u) : "f"(x));
    return u;
}

__device__ __forceinline__ void mma_tf32(
    float& c0, float& c1, float& c2, float& c3,
    uint32_t a0, uint32_t a1, uint32_t a2, uint32_t a3,
    uint32_t b0, uint32_t b1)
{
    asm volatile(
        "mma.sync.aligned.m16n8k8.row.col.f32.tf32.tf32.f32 "
        "{%0,%1,%2,%3}, {%4,%5,%6,%7}, {%8,%9}, {%0,%1,%2,%3};\n"
        : "+f"(c0), "+f"(c1), "+f"(c2), "+f"(c3)
        : "r"(a0), "r"(a1), "r"(a2), "r"(a3), "r"(b0), "r"(b1));
}

// ---------------------------------------------------------------------------
// TF32 GEMM 128x128x32, 256 threads (8 warps, 2x4), warp tile 64x32.
// As: [m][k] stride 36 (banks 4m+k -> conflict free)
// Bs: [k][n] stride 136 (banks 8k+n -> conflict free)
// ---------------------------------------------------------------------------
#define ASTR 36
#define BSTR 136

struct GemmAcc { float c[4][4][4]; };   // [mf][nf][reg]

__device__ __forceinline__ void gemm_body(
    const float* __restrict__ Aglob,  // row-major [*, K], base at (m0, 0)
    const float* __restrict__ Bglob,  // row-major [K, DOUT], base at (0, n0)
    int K, GemmAcc& acc,
    uint32_t* As, uint32_t* Bs)
{
    const int t    = threadIdx.x;
    const int wid  = t >> 5, lane = t & 31;
    const int lr   = lane >> 2, lc = lane & 3;
    const int wm   = (wid & 1) * 64;
    const int wn   = (wid >> 1) * 32;
    const int arow = t >> 3, acol = (t & 7) * 4;
    const int brow = t >> 5, bcol = (t & 31) * 4;

    #pragma unroll
    for (int mf = 0; mf < 4; mf++)
        #pragma unroll
        for (int nf = 0; nf < 4; nf++)
            #pragma unroll
            for (int r = 0; r < 4; r++) acc.c[mf][nf][r] = 0.f;

    const float* Ap = Aglob + arow * K + acol;
    const float* Bp = Bglob + brow * DOUT + bcol;

    float4 pa[4], pb[4];
    #pragma unroll
    for (int p = 0; p < 4; p++) {
        pa[p] = *(const float4*)(Ap + p * 32 * K);
        pb[p] = *(const float4*)(Bp + (size_t)(p * 8) * DOUT);
    }

    int k0 = 0;
    for (;;) {
        #pragma unroll
        for (int p = 0; p < 4; p++) {
            uint32_t* as = &As[(arow + 32 * p) * ASTR + acol];
            as[0] = f2tf(pa[p].x); as[1] = f2tf(pa[p].y);
            as[2] = f2tf(pa[p].z); as[3] = f2tf(pa[p].w);
            uint32_t* bs = &Bs[(brow + 8 * p) * BSTR + bcol];
            bs[0] = f2tf(pb[p].x); bs[1] = f2tf(pb[p].y);
            bs[2] = f2tf(pb[p].z); bs[3] = f2tf(pb[p].w);
        }
        __syncthreads();

        k0 += 32;
        const bool more = (k0 < K);
        if (more) {
            #pragma unroll
            for (int p = 0; p < 4; p++) {
                pa[p] = *(const float4*)(Ap + p * 32 * K + k0);
                pb[p] = *(const float4*)(Bp + (size_t)(k0 + p * 8) * DOUT);
            }
        }

        #pragma unroll
        for (int ks = 0; ks < 4; ks++) {
            const int kb = ks * 8;
            uint32_t a[4][4];
            #pragma unroll
            for (int mf = 0; mf < 4; mf++) {
                int r = wm + mf * 16 + lr;
                a[mf][0] = As[r * ASTR + kb + lc];
                a[mf][1] = As[(r + 8) * ASTR + kb + lc];
                a[mf][2] = As[r * ASTR + kb + lc + 4];
                a[mf][3] = As[(r + 8) * ASTR + kb + lc + 4];
            }
            uint32_t b[4][2];
            #pragma unroll
            for (int nf = 0; nf < 4; nf++) {
                int c = wn + nf * 8 + lr;
                b[nf][0] = Bs[(kb + lc) * BSTR + c];
                b[nf][1] = Bs[(kb + lc + 4) * BSTR + c];
            }
            #pragma unroll
            for (int mf = 0; mf < 4; mf++)
                #pragma unroll
                for (int nf = 0; nf < 4; nf++)
                    mma_tf32(acc.c[mf][nf][0], acc.c[mf][nf][1],
                             acc.c[mf][nf][2], acc.c[mf][nf][3],
                             a[mf][0], a[mf][1], a[mf][2], a[mf][3],
                             b[nf][0], b[nf][1]);
        }
        if (!more) break;
        __syncthreads();
    }
}

// qkv: z selects Wq/Wk/Wv; epilogue scatters into [B,H,N,HD]
__global__ __launch_bounds__(256) void qkv_gemm(
    const float* __restrict__ x,
    const float* __restrict__ Wq,
    const float* __restrict__ Wk,
    const float* __restrict__ Wv)
{
    __shared__ uint32_t As[128 * ASTR];
    __shared__ uint32_t Bs[32 * BSTR];

    const float* W   = (blockIdx.z == 0) ? Wq : (blockIdx.z == 1) ? Wk : Wv;
    float*       dst = (blockIdx.z == 0) ? g_q : (blockIdx.z == 1) ? g_k : g_v;

    const int m0 = blockIdx.y * 128, n0 = blockIdx.x * 128;
    GemmAcc acc;
    gemm_body(x + (size_t)m0 * DIN, W + n0, DIN, acc, As, Bs);

    const int t = threadIdx.x, wid = t >> 5, lane = t & 31;
    const int lr = lane >> 2, lc = lane & 3;
    const int wm = (wid & 1) * 64, wn = (wid >> 1) * 32;

    #pragma unroll
    for (int mf = 0; mf < 4; mf++) {
        #pragma unroll
        for (int nf = 0; nf < 4; nf++) {
            int cb = n0 + wn + nf * 8 + 2 * lc;
            int h = cb >> 6, d = cb & 63;
            #pragma unroll
            for (int half = 0; half < 2; half++) {
                int m = m0 + wm + mf * 16 + lr + half * 8;
                int b = m >> 11, n = m & 2047;
                float2 v = make_float2(acc.c[mf][nf][half * 2],
                                       acc.c[mf][nf][half * 2 + 1]);
                *(float2*)&dst[(((b << 4) + h) * SEQ + n) * HD + d] = v;
            }
        }
    }
}

// proj: out = ctx @ Wo + bo
__global__ __launch_bounds__(256) void proj_gemm(
    const float* __restrict__ Wo,
    const float* __restrict__ bo,
    float* __restrict__ out)
{
    __shared__ uint32_t As[128 * ASTR];
    __shared__ uint32_t Bs[32 * BSTR];

    const int m0 = blockIdx.y * 128, n0 = blockIdx.x * 128;
    GemmAcc acc;
    gemm_body(g_ctx + (size_t)m0 * DOUT, Wo + n0, DOUT, acc, As, Bs);

    const int t = threadIdx.x, wid = t >> 5, lane = t & 31;
    const int lr = lane >> 2, lc = lane & 3;
    const int wm = (wid & 1) * 64, wn = (wid >> 1) * 32;

    #pragma unroll
    for (int mf = 0; mf < 4; mf++) {
        #pragma unroll
        for (int nf = 0; nf < 4; nf++) {
            int cb = n0 + wn + nf * 8 + 2 * lc;
            float2 bias = *(const float2*)&bo[cb];
            #pragma unroll
            for (int half = 0; half < 2; half++) {
                int m = m0 + wm + mf * 16 + lr + half * 8;
                float2 v = make_float2(acc.c[mf][nf][half * 2] + bias.x,
                                       acc.c[mf][nf][half * 2 + 1] + bias.y);
                *(float2*)&out[m * DOUT + cb] = v;
            }
        }
    }
}

// ---------------------------------------------------------------------------
// TF32 flash attention. Q tile 128 (scale folded in), K/V chunks 64.
// 8 warps; warp w owns rows w*16..w*16+15.
// Qs[i][d] stride 68, Ks[d][j] stride 72, Vs[j][c] stride 72, Ps[i][j] stride 68.
// ---------------------------------------------------------------------------
#define QSTR 68
#define KSTR 72
#define VSTR 72
#define PSTR 68
#define ATTN_SMEM ((128*QSTR + 64*KSTR + 64*VSTR + 128*PSTR) * 4)

__global__ __launch_bounds__(256) void attn_kernel()
{
    extern __shared__ uint32_t smu[];
    uint32_t* Qs = smu;                       // [128][QSTR]
    uint32_t* Ks = Qs + 128 * QSTR;           // [64][KSTR]  (transposed: [d][j])
    uint32_t* Vs = Ks + 64 * KSTR;            // [64][VSTR]  ([j][c])
    uint32_t* Ps = Vs + 64 * VSTR;            // [128][PSTR]

    const int t    = threadIdx.x;
    const int wid  = t >> 5, lane = t & 31;
    const int lr   = lane >> 2, lc = lane & 3;
    const int tile = (gridDim.x - 1) - blockIdx.x;   // heavy tiles first
    const int bh   = blockIdx.y;
    const int q0   = tile * 128;

    const float* qbase = g_q + (size_t)(bh * SEQ + q0) * HD;
    const float* kbase = g_k + (size_t)bh * SEQ * HD;
    const float* vbase = g_v + (size_t)bh * SEQ * HD;

    // load Q (scaled by 1/sqrt(HD) = 0.125, tf32)
    #pragma unroll
    for (int it = 0; it < 8; it++) {
        int row = (t >> 4) + it * 16;
        int c4  = (t & 15) * 4;
        float4 v = *(const float4*)&qbase[row * HD + c4];
        uint32_t* q = &Qs[row * QSTR + c4];
        q[0] = f2tf(v.x * 0.125f); q[1] = f2tf(v.y * 0.125f);
        q[2] = f2tf(v.z * 0.125f); q[3] = f2tf(v.w * 0.125f);
    }

    float m0r = -1e30f, m1r = -1e30f, l0 = 0.f, l1 = 0.f;
    float o[8][4];
    #pragma unroll
    for (int nf = 0; nf < 8; nf++)
        #pragma unroll
        for (int r = 0; r < 4; r++) o[nf][r] = 0.f;

    const int nchunks = (q0 + 128) / 64;
    for (int ch = 0; ch < nchunks; ch++) {
        const int kb = ch * 64;
        __syncthreads();   // previous chunk's reads of Ks/Vs done

        // stage K transposed + V natural, tf32
        #pragma unroll
        for (int it = 0; it < 4; it++) {
            int j  = (t >> 4) + it * 16;
            int c4 = (t & 15) * 4;
            float4 kv = *(const float4*)&kbase[(kb + j) * HD + c4];
            Ks[(c4 + 0) * KSTR + j] = f2tf(kv.x);
            Ks[(c4 + 1) * KSTR + j] = f2tf(kv.y);
            Ks[(c4 + 2) * KSTR + j] = f2tf(kv.z);
            Ks[(c4 + 3) * KSTR + j] = f2tf(kv.w);
            float4 vv = *(const float4*)&vbase[(kb + j) * HD + c4];
            uint32_t* vs = &Vs[j * VSTR + c4];
            vs[0] = f2tf(vv.x); vs[1] = f2tf(vv.y);
            vs[2] = f2tf(vv.z); vs[3] = f2tf(vv.w);
        }
        __syncthreads();

        // S = Q K^T for this warp's 16 rows x 64 cols
        float s[8][4];
        #pragma unroll
        for (int nf = 0; nf < 8; nf++)
            #pragma unroll
            for (int r = 0; r < 4; r++) s[nf][r] = 0.f;

        #pragma unroll
        for (int ks = 0; ks < 8; ks++) {
            const int d0 = ks * 8;
            int r = wid * 16 + lr;
            uint32_t a0 = Qs[r * QSTR + d0 + lc];
            uint32_t a1 = Qs[(r + 8) * QSTR + d0 + lc];
            uint32_t a2 = Qs[r * QSTR + d0 + lc + 4];
            uint32_t a3 = Qs[(r + 8) * QSTR + d0 + lc + 4];
            #pragma unroll
            for (int nf = 0; nf < 8; nf++) {
                uint32_t b0 = Ks[(d0 + lc) * KSTR + nf * 8 + lr];
                uint32_t b1 = Ks[(d0 + lc + 4) * KSTR + nf * 8 + lr];
                mma_tf32(s[nf][0], s[nf][1], s[nf][2], s[nf][3],
                         a0, a1, a2, a3, b0, b1);
            }
        }

        // causal mask (only diagonal chunks)
        if (kb >= q0) {
            int r0 = q0 + wid * 16 + lr, r1 = r0 + 8;
            #pragma unroll
            for (int nf = 0; nf < 8; nf++) {
                int c0 = kb + nf * 8 + 2 * lc, c1 = c0 + 1;
                if (c0 > r0) s[nf][0] = -1e30f;
                if (c1 > r0) s[nf][1] = -1e30f;
                if (c0 > r1) s[nf][2] = -1e30f;
                if (c1 > r1) s[nf][3] = -1e30f;
            }
        }

        // online softmax for the thread's two rows
        float mx0 = -1e30f, mx1 = -1e30f;
        #pragma unroll
        for (int nf = 0; nf < 8; nf++) {
            mx0 = fmaxf(mx0, fmaxf(s[nf][0], s[nf][1]));
            mx1 = fmaxf(mx1, fmaxf(s[nf][2], s[nf][3]));
        }
        #pragma unroll
        for (int off = 1; off < 4; off <<= 1) {
            mx0 = fmaxf(mx0, __shfl_xor_sync(0xffffffffu, mx0, off));
            mx1 = fmaxf(mx1, __shfl_xor_sync(0xffffffffu, mx1, off));
        }
        float mn0 = fmaxf(m0r, mx0), mn1 = fmaxf(m1r, mx1);
        float sc0 = __expf(m0r - mn0), sc1 = __expf(m1r - mn1);
        m0r = mn0; m1r = mn1;

        float rs0 = 0.f, rs1 = 0.f;
        const int prow0 = (wid * 16 + lr) * PSTR;
        const int prow1 = prow0 + 8 * PSTR;
        #pragma unroll
        for (int nf = 0; nf < 8; nf++) {
            float p0 = __expf(s[nf][0] - mn0);
            float p1 = __expf(s[nf][1] - mn0);
            float p2 = __expf(s[nf][2] - mn1);
            float p3 = __expf(s[nf][3] - mn1);
            rs0 += p0 + p1; rs1 += p2 + p3;
            int cofs = nf * 8 + 2 * lc;
            uint2 w0 = make_uint2(f2tf(p0), f2tf(p1));
            uint2 w1 = make_uint2(f2tf(p2), f2tf(p3));
            *(uint2*)&Ps[prow0 + cofs] = w0;
            *(uint2*)&Ps[prow1 + cofs] = w1;
            o[nf][0] *= sc0; o[nf][1] *= sc0;
            o[nf][2] *= sc1; o[nf][3] *= sc1;
        }
        #pragma unroll
        for (int off = 1; off < 4; off <<= 1) {
            rs0 += __shfl_xor_sync(0xffffffffu, rs0, off);
            rs1 += __shfl_xor_sync(0xffffffffu, rs1, off);
        }
        l0 = l0 * sc0 + rs0;
        l1 = l1 * sc1 + rs1;

        __syncwarp();

        // O += P @ V
        #pragma unroll
        for (int ks = 0; ks < 8; ks++) {
            const int k0 = ks * 8;
            int r = wid * 16 + lr;
            uint32_t a0 = Ps[r * PSTR + k0 + lc];
            uint32_t a1 = Ps[(r + 8) * PSTR + k0 + lc];
            uint32_t a2 = Ps[r * PSTR + k0 + lc + 4];
            uint32_t a3 = Ps[(r + 8) * PSTR + k0 + lc + 4];
            #pragma unroll
            for (int nf = 0; nf < 8; nf++) {
                uint32_t b0 = Vs[(k0 + lc) * VSTR + nf * 8 + lr];
                uint32_t b1 = Vs[(k0 + lc + 4) * VSTR + nf * 8 + lr];
                mma_tf32(o[nf][0], o[nf][1], o[nf][2], o[nf][3],
                         a0, a1, a2, a3, b0, b1);
            }
        }
    }

    // epilogue: normalize and store to g_ctx
    const float inv0 = 1.f / l0, inv1 = 1.f / l1;
    const int b = bh >> 4, h = bh & 15;
    const int r0 = q0 + wid * 16 + lr, r1 = r0 + 8;
    #pragma unroll
    for (int nf = 0; nf < 8; nf++) {
        int cb = h * HD + nf * 8 + 2 * lc;
        *(float2*)&g_ctx[(size_t)(b * SEQ + r0) * DOUT + cb] =
            make_float2(o[nf][0] * inv0, o[nf][1] * inv0);
        *(float2*)&g_ctx[(size_t)(b * SEQ + r1) * DOUT + cb] =
            make_float2(o[nf][2] * inv1, o[nf][3] * inv1);
    }
}

// ---------------------------------------------------------------------------
extern "C" void kernel_launch(void* const* d_in, const int* in_sizes, int n_in,
                              void* d_out, int out_size)
{
    const float* x  = (const float*)d_in[0];
    const float* Wq = (const float*)d_in[1];
    const float* Wk = (const float*)d_in[2];
    const float* Wv = (const float*)d_in[3];
    const float* Wo = (const float*)d_in[4];
    const float* bo = (const float*)d_in[5];
    float* out = (float*)d_out;

    cudaFuncSetAttribute(attn_kernel,
                         cudaFuncAttributeMaxDynamicSharedMemorySize, ATTN_SMEM);

    qkv_gemm<<<dim3(DOUT / 128, MROWS / 128, 3), 256>>>(x, Wq, Wk, Wv);
    attn_kernel<<<dim3(SEQ / 128, BB * NH), 256, ATTN_SMEM>>>();
    proj_gemm<<<dim3(DOUT / 128, MROWS / 128), 256>>>(Wo, bo, out);
}

// round 5
// speedup vs baseline: 5.2700x; 1.1855x over previous
#include <cuda_runtime.h>
#include <cuda_bf16.h>
#include <cstdint>

#define BB   2
#define SEQ  2048
#define DIN  1024
#define DOUT 1024
#define NH   16
#define HD   64
#define MROWS (BB*SEQ)   // 4096

// Scratch (allocation-free requirement -> __device__ globals)
__device__ float g_q[BB*NH*SEQ*HD];    // [B,H,N,HD]  tf32-rounded, q pre-scaled
__device__ float g_k[BB*NH*SEQ*HD];
__device__ float g_v[BB*NH*SEQ*HD];
__device__ float g_ctx[MROWS*DOUT];    // [B*N, DOUT] tf32-rounded
__device__ float g_wr[4*DIN*DOUT];     // tf32-rounded weights [K,N] (q,k,v,o)

// ---------------------------------------------------------------------------
// helpers
// ---------------------------------------------------------------------------
__device__ __forceinline__ uint32_t f2tf(float x) {
    uint32_t u;
    asm("cvt.rna.tf32.f32 %0, %1;" : "=r"(u) : "f"(x));
    return u;
}

__device__ __forceinline__ uint32_t smem_u32(const void* p) {
    uint32_t a;
    asm("{ .reg .u64 t; cvta.to.shared.u64 t, %1; cvt.u32.u64 %0, t; }"
        : "=r"(a) : "l"(p));
    return a;
}

#define CP16(dst, src) \
    asm volatile("cp.async.cg.shared.global [%0], [%1], 16;" \
                 :: "r"(dst), "l"(src) : "memory")
#define CP_COMMIT() asm volatile("cp.async.commit_group;" ::: "memory")
#define CP_WAIT0()  asm volatile("cp.async.wait_group 0;" ::: "memory")

__device__ __forceinline__ void mma_tf32(
    float& c0, float& c1, float& c2, float& c3,
    uint32_t a0, uint32_t a1, uint32_t a2, uint32_t a3,
    uint32_t b0, uint32_t b1)
{
    asm volatile(
        "mma.sync.aligned.m16n8k8.row.col.f32.tf32.tf32.f32 "
        "{%0,%1,%2,%3}, {%4,%5,%6,%7}, {%8,%9}, {%0,%1,%2,%3};\n"
        : "+f"(c0), "+f"(c1), "+f"(c2), "+f"(c3)
        : "r"(a0), "r"(a1), "r"(a2), "r"(a3), "r"(b0), "r"(b1));
}

// ---------------------------------------------------------------------------
// Weight rounding: W[K,N] -> g_wr[z][K,N], tf32-rounded bit patterns.
// grid (1024, 4), block 256
// ---------------------------------------------------------------------------
__global__ __launch_bounds__(256) void round_w(
    const float* __restrict__ Wq, const float* __restrict__ Wk,
    const float* __restrict__ Wv, const float* __restrict__ Wo)
{
    const float* src = (blockIdx.y == 0) ? Wq : (blockIdx.y == 1) ? Wk :
                       (blockIdx.y == 2) ? Wv : Wo;
    float* dst = g_wr + ((size_t)blockIdx.y << 20);
    size_t i = ((size_t)blockIdx.x * 256 + threadIdx.x) * 4;
    float4 v = *(const float4*)(src + i);
    uint4 r = make_uint4(f2tf(v.x), f2tf(v.y), f2tf(v.z), f2tf(v.w));
    *(uint4*)(dst + i) = r;
}

// ---------------------------------------------------------------------------
// cp.async pipelined TF32 HMMA GEMM, tile 128x128x32, 256 thr, 2 stages.
// As raw/pre-rounded [128][36 words], Bs pre-rounded [32][136 words].
// ---------------------------------------------------------------------------
#define ASTR 36
#define BSTR 136
#define A_BYTES (128 * ASTR * 4)      // 18432
#define B_BYTES (32 * BSTR * 4)       // 17408
#define STAGE_B (A_BYTES + B_BYTES)   // 35840
#define GEMM_SMEM (2 * STAGE_B)       // 71680

struct GemmAcc { float c[4][4][4]; };

__device__ __forceinline__ void gemm_cp_body(
    const float* __restrict__ Ag,   // base row m0, lda=1024
    const float* __restrict__ Bg,   // base col n0 of [K,1024]
    bool cvtA, GemmAcc& acc, char* sm)
{
    const int t    = threadIdx.x;
    const int wid  = t >> 5, lane = t & 31;
    const int lr   = lane >> 2, lc = lane & 3;
    const int wm   = (wid & 1) * 64;
    const int wn   = (wid >> 1) * 32;
    const uint32_t sb0 = smem_u32(sm);

    #pragma unroll
    for (int mf = 0; mf < 4; mf++)
        #pragma unroll
        for (int nf = 0; nf < 4; nf++)
            #pragma unroll
            for (int r = 0; r < 4; r++) acc.c[mf][nf][r] = 0.f;

    uint32_t adst[4], bdst[4];
    const float* asrc[4];
    const float* bsrc[4];
    #pragma unroll
    for (int i = 0; i < 4; i++) {
        int c = t + i * 256;
        int ar = c >> 3, ak = c & 7;
        adst[i] = ar * 144 + ak * 16;
        asrc[i] = Ag + (size_t)ar * 1024 + ak * 4;
        int br = c >> 5, bn = c & 31;
        bdst[i] = A_BYTES + br * 544 + bn * 16;
        bsrc[i] = Bg + (size_t)br * 1024 + bn * 4;
    }

    // prologue: stage 0 = ktile 0
    #pragma unroll
    for (int i = 0; i < 4; i++) {
        CP16(sb0 + adst[i], asrc[i]);
        CP16(sb0 + bdst[i], bsrc[i]);
    }
    CP_COMMIT();

    for (int kt = 0; kt < 32; kt++) {
        CP_WAIT0();
        __syncthreads();
        if (kt + 1 < 32) {
            const uint32_t sn = sb0 + ((kt + 1) & 1) * STAGE_B;
            #pragma unroll
            for (int i = 0; i < 4; i++) {
                CP16(sn + adst[i], asrc[i] + (kt + 1) * 32);
                CP16(sn + bdst[i], bsrc[i] + (size_t)(kt + 1) * 32 * 1024);
            }
            CP_COMMIT();
        }

        const uint32_t* As = (const uint32_t*)(sm + (kt & 1) * STAGE_B);
        const uint32_t* Bs = (const uint32_t*)(sm + (kt & 1) * STAGE_B + A_BYTES);

        #pragma unroll
        for (int ks = 0; ks < 4; ks++) {
            const int kb = ks * 8;
            uint32_t a[4][4];
            #pragma unroll
            for (int mf = 0; mf < 4; mf++) {
                int r = wm + mf * 16 + lr;
                a[mf][0] = As[r * ASTR + kb + lc];
                a[mf][1] = As[(r + 8) * ASTR + kb + lc];
                a[mf][2] = As[r * ASTR + kb + lc + 4];
                a[mf][3] = As[(r + 8) * ASTR + kb + lc + 4];
                if (cvtA) {
                    a[mf][0] = f2tf(__uint_as_float(a[mf][0]));
                    a[mf][1] = f2tf(__uint_as_float(a[mf][1]));
                    a[mf][2] = f2tf(__uint_as_float(a[mf][2]));
                    a[mf][3] = f2tf(__uint_as_float(a[mf][3]));
                }
            }
            uint32_t b[4][2];
            #pragma unroll
            for (int nf = 0; nf < 4; nf++) {
                int c = wn + nf * 8 + lr;
                b[nf][0] = Bs[(kb + lc) * BSTR + c];
                b[nf][1] = Bs[(kb + lc + 4) * BSTR + c];
            }
            #pragma unroll
            for (int mf = 0; mf < 4; mf++)
                #pragma unroll
                for (int nf = 0; nf < 4; nf++)
                    mma_tf32(acc.c[mf][nf][0], acc.c[mf][nf][1],
                             acc.c[mf][nf][2], acc.c[mf][nf][3],
                             a[mf][0], a[mf][1], a[mf][2], a[mf][3],
                             b[nf][0], b[nf][1]);
        }
        __syncthreads();
    }
}

// qkv: z selects weight + destination; writes tf32-rounded (q pre-scaled 0.125)
__global__ __launch_bounds__(256, 2) void qkv_gemm(const float* __restrict__ x)
{
    extern __shared__ char sm[];
    const int m0 = blockIdx.y * 128, n0 = blockIdx.x * 128;
    GemmAcc acc;
    gemm_cp_body(x + (size_t)m0 * DIN,
                 g_wr + ((size_t)blockIdx.z << 20) + n0, true, acc, sm);

    float* dst = (blockIdx.z == 0) ? g_q : (blockIdx.z == 1) ? g_k : g_v;
    const float qs = (blockIdx.z == 0) ? 0.125f : 1.0f;
    const int t = threadIdx.x, wid = t >> 5, lane = t & 31;
    const int lr = lane >> 2, lc = lane & 3;
    const int wm = (wid & 1) * 64, wn = (wid >> 1) * 32;

    #pragma unroll
    for (int mf = 0; mf < 4; mf++) {
        #pragma unroll
        for (int nf = 0; nf < 4; nf++) {
            int cb = n0 + wn + nf * 8 + 2 * lc;
            int h = cb >> 6, d = cb & 63;
            #pragma unroll
            for (int half = 0; half < 2; half++) {
                int m = m0 + wm + mf * 16 + lr + half * 8;
                int b = m >> 11, n = m & 2047;
                uint2 v = make_uint2(f2tf(acc.c[mf][nf][half*2] * qs),
                                     f2tf(acc.c[mf][nf][half*2+1] * qs));
                *(uint2*)&dst[(((size_t)(b * 16 + h) * SEQ + n)) * HD + d] = v;
            }
        }
    }
}

// proj: out = ctx @ Wo + bo (ctx pre-rounded -> no cvt)
__global__ __launch_bounds__(256, 2) void proj_gemm(
    const float* __restrict__ bo, float* __restrict__ out)
{
    extern __shared__ char sm[];
    const int m0 = blockIdx.y * 128, n0 = blockIdx.x * 128;
    GemmAcc acc;
    gemm_cp_body(g_ctx + (size_t)m0 * DOUT,
                 g_wr + ((size_t)3 << 20) + n0, false, acc, sm);

    const int t = threadIdx.x, wid = t >> 5, lane = t & 31;
    const int lr = lane >> 2, lc = lane & 3;
    const int wm = (wid & 1) * 64, wn = (wid >> 1) * 32;

    #pragma unroll
    for (int mf = 0; mf < 4; mf++) {
        #pragma unroll
        for (int nf = 0; nf < 4; nf++) {
            int cb = n0 + wn + nf * 8 + 2 * lc;
            float2 bias = *(const float2*)&bo[cb];
            #pragma unroll
            for (int half = 0; half < 2; half++) {
                int m = m0 + wm + mf * 16 + lr + half * 8;
                *(float2*)&out[(size_t)m * DOUT + cb] =
                    make_float2(acc.c[mf][nf][half*2] + bias.x,
                                acc.c[mf][nf][half*2+1] + bias.y);
            }
        }
    }
}

// ---------------------------------------------------------------------------
// TF32 flash attention, cp.async double-buffered K/V (natural layout).
// Q tile 128 (pre-scaled/rounded), K/V chunks 64. 8 warps.
// Qs[i][d] s68, K[j][d] s68, V[j][d] s72, Ps[i][j] s68.
// ---------------------------------------------------------------------------
#define QSTR 68
#define KSTR 68
#define VSTR 72
#define PSTR 68
#define Q_WORDS (128*QSTR)
#define K_WORDS (64*KSTR)
#define V_WORDS (64*VSTR)
#define ATTN_SMEM ((Q_WORDS + 2*K_WORDS + 2*V_WORDS + 128*PSTR) * 4)

__global__ __launch_bounds__(256) void attn_kernel()
{
    extern __shared__ uint32_t smu[];
    uint32_t* Qs = smu;                          // [128][QSTR]
    uint32_t* Kb = Qs + Q_WORDS;                 // 2 x [64][KSTR]
    uint32_t* Vb = Kb + 2 * K_WORDS;             // 2 x [64][VSTR]
    uint32_t* Ps = Vb + 2 * V_WORDS;             // [128][PSTR]

    const int t    = threadIdx.x;
    const int wid  = t >> 5, lane = t & 31;
    const int lr   = lane >> 2, lc = lane & 3;
    const int tile = (gridDim.x - 1) - blockIdx.x;   // heavy tiles first
    const int bh   = blockIdx.y;
    const int q0   = tile * 128;

    const float* qbase = g_q + (size_t)(bh * SEQ + q0) * HD;
    const float* kbase = g_k + (size_t)bh * SEQ * HD;
    const float* vbase = g_v + (size_t)bh * SEQ * HD;

    const uint32_t qsm = smem_u32(Qs);
    const uint32_t ksm = smem_u32(Kb);
    const uint32_t vsm = smem_u32(Vb);

    // async copy Q (128 rows x 256B = 2048 chunks, 8/thread)
    #pragma unroll
    for (int i = 0; i < 8; i++) {
        int c = t + i * 256;
        int r = c >> 4, sb = c & 15;
        CP16(qsm + r * (QSTR*4) + sb * 16, qbase + (size_t)r * HD + sb * 4);
    }
    CP_COMMIT();

    // chunk staging: 64 rows x 256B each for K and V (4+4 chunks/thread)
    const int kr = t >> 2, kc = (t & 3) * 4;     // 4 rows per 16 threads? no:
    // mapping: chunk id c = t + i*256; r = c>>4, sb = c&15
    // prologue chunk 0
    {
        #pragma unroll
        for (int i = 0; i < 4; i++) {
            int c = t + i * 256;
            int r = c >> 4, sb = c & 15;
            CP16(ksm + r * (KSTR*4) + sb * 16, kbase + (size_t)r * HD + sb * 4);
            CP16(vsm + r * (VSTR*4) + sb * 16, vbase + (size_t)r * HD + sb * 4);
        }
        CP_COMMIT();
    }

    float m0r = -1e30f, m1r = -1e30f, l0 = 0.f, l1 = 0.f;
    float o[8][4];
    #pragma unroll
    for (int nf = 0; nf < 8; nf++)
        #pragma unroll
        for (int r = 0; r < 4; r++) o[nf][r] = 0.f;

    const int nchunks = (q0 + 128) / 64;
    for (int ch = 0; ch < nchunks; ch++) {
        const int kb = ch * 64;
        CP_WAIT0();
        __syncthreads();

        if (ch + 1 < nchunks) {
            const uint32_t ks2 = ksm + ((ch + 1) & 1) * (K_WORDS * 4);
            const uint32_t vs2 = vsm + ((ch + 1) & 1) * (V_WORDS * 4);
            const float* kp = kbase + (size_t)(kb + 64) * HD;
            const float* vp = vbase + (size_t)(kb + 64) * HD;
            #pragma unroll
            for (int i = 0; i < 4; i++) {
                int c = t + i * 256;
                int r = c >> 4, sb = c & 15;
                CP16(ks2 + r * (KSTR*4) + sb * 16, kp + (size_t)r * HD + sb * 4);
                CP16(vs2 + r * (VSTR*4) + sb * 16, vp + (size_t)r * HD + sb * 4);
            }
            CP_COMMIT();
        }

        const uint32_t* Ks = Kb + (ch & 1) * K_WORDS;
        const uint32_t* Vs = Vb + (ch & 1) * V_WORDS;

        // S = Q K^T for this warp's 16 rows x 64 cols
        float s[8][4];
        #pragma unroll
        for (int nf = 0; nf < 8; nf++)
            #pragma unroll
            for (int r = 0; r < 4; r++) s[nf][r] = 0.f;

        #pragma unroll
        for (int ks = 0; ks < 8; ks++) {
            const int d0 = ks * 8;
            int r = wid * 16 + lr;
            uint32_t a0 = Qs[r * QSTR + d0 + lc];
            uint32_t a1 = Qs[(r + 8) * QSTR + d0 + lc];
            uint32_t a2 = Qs[r * QSTR + d0 + lc + 4];
            uint32_t a3 = Qs[(r + 8) * QSTR + d0 + lc + 4];
            #pragma unroll
            for (int nf = 0; nf < 8; nf++) {
                uint32_t b0 = Ks[(nf * 8 + lr) * KSTR + d0 + lc];
                uint32_t b1 = Ks[(nf * 8 + lr) * KSTR + d0 + lc + 4];
                mma_tf32(s[nf][0], s[nf][1], s[nf][2], s[nf][3],
                         a0, a1, a2, a3, b0, b1);
            }
        }

        // causal mask (only diagonal chunks)
        if (kb >= q0) {
            int r0 = q0 + wid * 16 + lr, r1 = r0 + 8;
            #pragma unroll
            for (int nf = 0; nf < 8; nf++) {
                int c0 = kb + nf * 8 + 2 * lc, c1 = c0 + 1;
                if (c0 > r0) s[nf][0] = -1e30f;
                if (c1 > r0) s[nf][1] = -1e30f;
                if (c0 > r1) s[nf][2] = -1e30f;
                if (c1 > r1) s[nf][3] = -1e30f;
            }
        }

        // online softmax (thread's two rows; reduce across 4 lanes sharing row)
        float mx0 = -1e30f, mx1 = -1e30f;
        #pragma unroll
        for (int nf = 0; nf < 8; nf++) {
            mx0 = fmaxf(mx0, fmaxf(s[nf][0], s[nf][1]));
            mx1 = fmaxf(mx1, fmaxf(s[nf][2], s[nf][3]));
        }
        #pragma unroll
        for (int off = 1; off < 4; off <<= 1) {
            mx0 = fmaxf(mx0, __shfl_xor_sync(0xffffffffu, mx0, off));
            mx1 = fmaxf(mx1, __shfl_xor_sync(0xffffffffu, mx1, off));
        }
        float mn0 = fmaxf(m0r, mx0), mn1 = fmaxf(m1r, mx1);
        float sc0 = __expf(m0r - mn0), sc1 = __expf(m1r - mn1);
        m0r = mn0; m1r = mn1;

        float rs0 = 0.f, rs1 = 0.f;
        const int prow0 = (wid * 16 + lr) * PSTR;
        const int prow1 = prow0 + 8 * PSTR;
        #pragma unroll
        for (int nf = 0; nf < 8; nf++) {
            float p0 = __expf(s[nf][0] - mn0);
            float p1 = __expf(s[nf][1] - mn0);
            float p2 = __expf(s[nf][2] - mn1);
            float p3 = __expf(s[nf][3] - mn1);
            rs0 += p0 + p1; rs1 += p2 + p3;
            int cofs = nf * 8 + 2 * lc;
            *(uint2*)&Ps[prow0 + cofs] = make_uint2(f2tf(p0), f2tf(p1));
            *(uint2*)&Ps[prow1 + cofs] = make_uint2(f2tf(p2), f2tf(p3));
            o[nf][0] *= sc0; o[nf][1] *= sc0;
            o[nf][2] *= sc1; o[nf][3] *= sc1;
        }
        #pragma unroll
        for (int off = 1; off < 4; off <<= 1) {
            rs0 += __shfl_xor_sync(0xffffffffu, rs0, off);
            rs1 += __shfl_xor_sync(0xffffffffu, rs1, off);
        }
        l0 = l0 * sc0 + rs0;
        l1 = l1 * sc1 + rs1;

        __syncwarp();

        // O += P @ V
        #pragma unroll
        for (int ks = 0; ks < 8; ks++) {
            const int k0 = ks * 8;
            int r = wid * 16 + lr;
            uint32_t a0 = Ps[r * PSTR + k0 + lc];
            uint32_t a1 = Ps[(r + 8) * PSTR + k0 + lc];
            uint32_t a2 = Ps[r * PSTR + k0 + lc + 4];
            uint32_t a3 = Ps[(r + 8) * PSTR + k0 + lc + 4];
            #pragma unroll
            for (int nf = 0; nf < 8; nf++) {
                uint32_t b0 = Vs[(k0 + lc) * VSTR + nf * 8 + lr];
                uint32_t b1 = Vs[(k0 + lc + 4) * VSTR + nf * 8 + lr];
                mma_tf32(o[nf][0], o[nf][1], o[nf][2], o[nf][3],
                         a0, a1, a2, a3, b0, b1);
            }
        }
        __syncthreads();   // all warps done with Ks/Vs/Ps before refill/overwrite
    }

    // epilogue: normalize, tf32-round, store to g_ctx
    const float inv0 = 1.f / l0, inv1 = 1.f / l1;
    const int b = bh >> 4, h = bh & 15;
    const int r0 = q0 + wid * 16 + lr, r1 = r0 + 8;
    #pragma unroll
    for (int nf = 0; nf < 8; nf++) {
        int cb = h * HD + nf * 8 + 2 * lc;
        *(uint2*)&g_ctx[(size_t)(b * SEQ + r0) * DOUT + cb] =
            make_uint2(f2tf(o[nf][0] * inv0), f2tf(o[nf][1] * inv0));
        *(uint2*)&g_ctx[(size_t)(b * SEQ + r1) * DOUT + cb] =
            make_uint2(f2tf(o[nf][2] * inv1), f2tf(o[nf][3] * inv1));
    }
}

// ---------------------------------------------------------------------------
extern "C" void kernel_launch(void* const* d_in, const int* in_sizes, int n_in,
                              void* d_out, int out_size)
{
    const float* x  = (const float*)d_in[0];
    const float* Wq = (const float*)d_in[1];
    const float* Wk = (const float*)d_in[2];
    const float* Wv = (const float*)d_in[3];
    const float* Wo = (const float*)d_in[4];
    const float* bo = (const float*)d_in[5];
    float* out = (float*)d_out;

    cudaFuncSetAttribute(attn_kernel,
                         cudaFuncAttributeMaxDynamicSharedMemorySize, ATTN_SMEM);
    cudaFuncSetAttribute(qkv_gemm,
                         cudaFuncAttributeMaxDynamicSharedMemorySize, GEMM_SMEM);
    cudaFuncSetAttribute(proj_gemm,
                         cudaFuncAttributeMaxDynamicSharedMemorySize, GEMM_SMEM);

    round_w<<<dim3(1024, 4), 256>>>(Wq, Wk, Wv, Wo);
    qkv_gemm<<<dim3(DOUT / 128, MROWS / 128, 3), 256, GEMM_SMEM>>>(x);
    attn_kernel<<<dim3(SEQ / 128, BB * NH), 256, ATTN_SMEM>>>();
    proj_gemm<<<dim3(DOUT / 128, MROWS / 128), 256, GEMM_SMEM>>>(bo, out);
}

// round 6
// speedup vs baseline: 5.4376x; 1.0318x over previous
#include <cuda_runtime.h>
#include <cuda_bf16.h>
#include <cstdint>

#define BB   2
#define SEQ  2048
#define DIN  1024
#define DOUT 1024
#define NH   16
#define HD   64
#define MROWS (BB*SEQ)   // 4096

// Scratch (allocation-free requirement -> __device__ globals)
__device__ float g_q[BB*NH*SEQ*HD];    // [B,H,N,HD] tf32-rounded, q pre-scaled by 0.125*log2e
__device__ float g_k[BB*NH*SEQ*HD];
__device__ float g_v[BB*NH*SEQ*HD];
__device__ float g_ctx[MROWS*DOUT];    // [B*N, DOUT] tf32-rounded
__device__ float g_wr[4*DIN*DOUT];     // tf32-rounded weights [K,N] (q,k,v,o)
__device__ float g_xr[MROWS*DIN];      // tf32-rounded x

#define QSCALE 0.1803368801111713f     // 0.125 * log2(e)

// ---------------------------------------------------------------------------
// helpers
// ---------------------------------------------------------------------------
__device__ __forceinline__ uint32_t f2tf(float x) {
    uint32_t u;
    asm("cvt.rna.tf32.f32 %0, %1;" : "=r"(u) : "f"(x));
    return u;
}

__device__ __forceinline__ uint32_t smem_u32(const void* p) {
    uint32_t a;
    asm("{ .reg .u64 t; cvta.to.shared.u64 t, %1; cvt.u32.u64 %0, t; }"
        : "=r"(a) : "l"(p));
    return a;
}

#define CP16(dst, src) \
    asm volatile("cp.async.cg.shared.global [%0], [%1], 16;" \
                 :: "r"(dst), "l"(src) : "memory")
#define CP_COMMIT() asm volatile("cp.async.commit_group;" ::: "memory")
#define CP_WAIT0()  asm volatile("cp.async.wait_group 0;" ::: "memory")

__device__ __forceinline__ void mma_tf32(
    float& c0, float& c1, float& c2, float& c3,
    uint32_t a0, uint32_t a1, uint32_t a2, uint32_t a3,
    uint32_t b0, uint32_t b1)
{
    asm volatile(
        "mma.sync.aligned.m16n8k8.row.col.f32.tf32.tf32.f32 "
        "{%0,%1,%2,%3}, {%4,%5,%6,%7}, {%8,%9}, {%0,%1,%2,%3};\n"
        : "+f"(c0), "+f"(c1), "+f"(c2), "+f"(c3)
        : "r"(a0), "r"(a1), "r"(a2), "r"(a3), "r"(b0), "r"(b1));
}

// ---------------------------------------------------------------------------
// Pre-rounding kernels
// ---------------------------------------------------------------------------
__global__ __launch_bounds__(256) void round_w(
    const float* __restrict__ Wq, const float* __restrict__ Wk,
    const float* __restrict__ Wv, const float* __restrict__ Wo)
{
    const float* src = (blockIdx.y == 0) ? Wq : (blockIdx.y == 1) ? Wk :
                       (blockIdx.y == 2) ? Wv : Wo;
    float* dst = g_wr + ((size_t)blockIdx.y << 20);
    size_t i = ((size_t)blockIdx.x * 256 + threadIdx.x) * 4;
    float4 v = *(const float4*)(src + i);
    *(uint4*)(dst + i) = make_uint4(f2tf(v.x), f2tf(v.y), f2tf(v.z), f2tf(v.w));
}

__global__ __launch_bounds__(256) void round_x(const float* __restrict__ x)
{
    size_t i = ((size_t)blockIdx.x * 256 + threadIdx.x) * 4;
    float4 v = *(const float4*)(x + i);
    *(uint4*)(g_xr + i) = make_uint4(f2tf(v.x), f2tf(v.y), f2tf(v.z), f2tf(v.w));
}

// ---------------------------------------------------------------------------
// cp.async pipelined TF32 HMMA GEMM, tile 256x128x32, 256 thr, 2 stages.
// Warp grid 4(M) x 2(N), warp tile 64x64.
// As [256][36 words], Bs [32][136 words] (both conflict-free for fragments).
// ---------------------------------------------------------------------------
#define ASTR 36
#define BSTR 136
#define A_BYTES (256 * ASTR * 4)      // 36864
#define B_BYTES (32 * BSTR * 4)       // 17408
#define STAGE_B (A_BYTES + B_BYTES)   // 54272
#define GEMM_SMEM (2 * STAGE_B)       // 108544

struct GemmAcc { float c[4][8][4]; };  // [mf][nf][reg]

__device__ __forceinline__ void gemm_cp_body(
    const float* __restrict__ Ag,   // base row m0 (pre-rounded), lda=1024
    const float* __restrict__ Bg,   // base col n0 of [K,1024] (pre-rounded)
    GemmAcc& acc, char* sm)
{
    const int t    = threadIdx.x;
    const int wid  = t >> 5, lane = t & 31;
    const int lr   = lane >> 2, lc = lane & 3;
    const int wm   = (wid & 3) * 64;
    const int wn   = (wid >> 2) * 64;
    const uint32_t sb0 = smem_u32(sm);

    #pragma unroll
    for (int mf = 0; mf < 4; mf++)
        #pragma unroll
        for (int nf = 0; nf < 8; nf++)
            #pragma unroll
            for (int r = 0; r < 4; r++) acc.c[mf][nf][r] = 0.f;

    uint32_t adst[8], bdst[4];
    const float* asrc[8];
    const float* bsrc[4];
    #pragma unroll
    for (int i = 0; i < 8; i++) {
        int c = t + i * 256;
        int ar = c >> 3, ak = c & 7;
        adst[i] = ar * (ASTR * 4) + ak * 16;
        asrc[i] = Ag + (size_t)ar * 1024 + ak * 4;
    }
    #pragma unroll
    for (int i = 0; i < 4; i++) {
        int c = t + i * 256;
        int br = c >> 5, bn = c & 31;
        bdst[i] = A_BYTES + br * (BSTR * 4) + bn * 16;
        bsrc[i] = Bg + (size_t)br * 1024 + bn * 4;
    }

    // prologue: stage 0 = ktile 0
    #pragma unroll
    for (int i = 0; i < 8; i++) CP16(sb0 + adst[i], asrc[i]);
    #pragma unroll
    for (int i = 0; i < 4; i++) CP16(sb0 + bdst[i], bsrc[i]);
    CP_COMMIT();

    for (int kt = 0; kt < 32; kt++) {
        CP_WAIT0();
        __syncthreads();
        if (kt + 1 < 32) {
            const uint32_t sn = sb0 + ((kt + 1) & 1) * STAGE_B;
            #pragma unroll
            for (int i = 0; i < 8; i++)
                CP16(sn + adst[i], asrc[i] + (kt + 1) * 32);
            #pragma unroll
            for (int i = 0; i < 4; i++)
                CP16(sn + bdst[i], bsrc[i] + (size_t)(kt + 1) * 32 * 1024);
            CP_COMMIT();
        }

        const uint32_t* As = (const uint32_t*)(sm + (kt & 1) * STAGE_B);
        const uint32_t* Bs = (const uint32_t*)(sm + (kt & 1) * STAGE_B + A_BYTES);

        #pragma unroll
        for (int ks = 0; ks < 4; ks++) {
            const int kb = ks * 8;
            uint32_t b[8][2];
            #pragma unroll
            for (int nf = 0; nf < 8; nf++) {
                int c = wn + nf * 8 + lr;
                b[nf][0] = Bs[(kb + lc) * BSTR + c];
                b[nf][1] = Bs[(kb + lc + 4) * BSTR + c];
            }
            #pragma unroll
            for (int mf = 0; mf < 4; mf++) {
                int r = wm + mf * 16 + lr;
                uint32_t a0 = As[r * ASTR + kb + lc];
                uint32_t a1 = As[(r + 8) * ASTR + kb + lc];
                uint32_t a2 = As[r * ASTR + kb + lc + 4];
                uint32_t a3 = As[(r + 8) * ASTR + kb + lc + 4];
                #pragma unroll
                for (int nf = 0; nf < 8; nf++)
                    mma_tf32(acc.c[mf][nf][0], acc.c[mf][nf][1],
                             acc.c[mf][nf][2], acc.c[mf][nf][3],
                             a0, a1, a2, a3, b[nf][0], b[nf][1]);
            }
        }
        __syncthreads();
    }
}

// qkv: z selects weight + destination; writes tf32-rounded (q pre-scaled)
__global__ __launch_bounds__(256, 1) void qkv_gemm()
{
    extern __shared__ char sm[];
    const int m0 = blockIdx.y * 256, n0 = blockIdx.x * 128;
    GemmAcc acc;
    gemm_cp_body(g_xr + (size_t)m0 * DIN,
                 g_wr + ((size_t)blockIdx.z << 20) + n0, acc, sm);

    float* dst = (blockIdx.z == 0) ? g_q : (blockIdx.z == 1) ? g_k : g_v;
    const float qs = (blockIdx.z == 0) ? QSCALE : 1.0f;
    const int t = threadIdx.x, wid = t >> 5, lane = t & 31;
    const int lr = lane >> 2, lc = lane & 3;
    const int wm = (wid & 3) * 64, wn = (wid >> 2) * 64;

    #pragma unroll
    for (int mf = 0; mf < 4; mf++) {
        #pragma unroll
        for (int nf = 0; nf < 8; nf++) {
            int cb = n0 + wn + nf * 8 + 2 * lc;
            int h = cb >> 6, d = cb & 63;
            #pragma unroll
            for (int half = 0; half < 2; half++) {
                int m = m0 + wm + mf * 16 + lr + half * 8;
                int b = m >> 11, n = m & 2047;
                uint2 v = make_uint2(f2tf(acc.c[mf][nf][half*2] * qs),
                                     f2tf(acc.c[mf][nf][half*2+1] * qs));
                *(uint2*)&dst[((size_t)(b * 16 + h) * SEQ + n) * HD + d] = v;
            }
        }
    }
}

// proj: out = ctx @ Wo + bo (ctx pre-rounded by attention)
__global__ __launch_bounds__(256, 1) void proj_gemm(
    const float* __restrict__ bo, float* __restrict__ out)
{
    extern __shared__ char sm[];
    const int m0 = blockIdx.y * 256, n0 = blockIdx.x * 128;
    GemmAcc acc;
    gemm_cp_body(g_ctx + (size_t)m0 * DOUT,
                 g_wr + ((size_t)3 << 20) + n0, acc, sm);

    const int t = threadIdx.x, wid = t >> 5, lane = t & 31;
    const int lr = lane >> 2, lc = lane & 3;
    const int wm = (wid & 3) * 64, wn = (wid >> 2) * 64;

    #pragma unroll
    for (int mf = 0; mf < 4; mf++) {
        #pragma unroll
        for (int nf = 0; nf < 8; nf++) {
            int cb = n0 + wn + nf * 8 + 2 * lc;
            float2 bias = *(const float2*)&bo[cb];
            #pragma unroll
            for (int half = 0; half < 2; half++) {
                int m = m0 + wm + mf * 16 + lr + half * 8;
                *(float2*)&out[(size_t)m * DOUT + cb] =
                    make_float2(acc.c[mf][nf][half*2] + bias.x,
                                acc.c[mf][nf][half*2+1] + bias.y);
            }
        }
    }
}

// ---------------------------------------------------------------------------
// TF32 flash attention, cp.async double-buffered K/V (natural layout).
// Q tile 128 (pre-scaled by 0.125*log2e -> exp2 softmax), K/V chunks 64.
// ---------------------------------------------------------------------------
#define QSTR 68
#define KSTR 68
#define VSTR 72
#define PSTR 68
#define Q_WORDS (128*QSTR)
#define K_WORDS (64*KSTR)
#define V_WORDS (64*VSTR)
#define ATTN_SMEM ((Q_WORDS + 2*K_WORDS + 2*V_WORDS + 128*PSTR) * 4)

__global__ __launch_bounds__(256) void attn_kernel()
{
    extern __shared__ uint32_t smu[];
    uint32_t* Qs = smu;                          // [128][QSTR]
    uint32_t* Kb = Qs + Q_WORDS;                 // 2 x [64][KSTR]
    uint32_t* Vb = Kb + 2 * K_WORDS;             // 2 x [64][VSTR]
    uint32_t* Ps = Vb + 2 * V_WORDS;             // [128][PSTR]

    const int t    = threadIdx.x;
    const int wid  = t >> 5, lane = t & 31;
    const int lr   = lane >> 2, lc = lane & 3;
    const int tile = (gridDim.x - 1) - blockIdx.x;   // heavy tiles first
    const int bh   = blockIdx.y;
    const int q0   = tile * 128;

    const float* qbase = g_q + (size_t)(bh * SEQ + q0) * HD;
    const float* kbase = g_k + (size_t)bh * SEQ * HD;
    const float* vbase = g_v + (size_t)bh * SEQ * HD;

    const uint32_t qsm = smem_u32(Qs);
    const uint32_t ksm = smem_u32(Kb);
    const uint32_t vsm = smem_u32(Vb);

    #pragma unroll
    for (int i = 0; i < 8; i++) {
        int c = t + i * 256;
        int r = c >> 4, sb = c & 15;
        CP16(qsm + r * (QSTR*4) + sb * 16, qbase + (size_t)r * HD + sb * 4);
    }
    CP_COMMIT();
    {
        #pragma unroll
        for (int i = 0; i < 4; i++) {
            int c = t + i * 256;
            int r = c >> 4, sb = c & 15;
            CP16(ksm + r * (KSTR*4) + sb * 16, kbase + (size_t)r * HD + sb * 4);
            CP16(vsm + r * (VSTR*4) + sb * 16, vbase + (size_t)r * HD + sb * 4);
        }
        CP_COMMIT();
    }

    float m0r = -1e30f, m1r = -1e30f, l0 = 0.f, l1 = 0.f;
    float o[8][4];
    #pragma unroll
    for (int nf = 0; nf < 8; nf++)
        #pragma unroll
        for (int r = 0; r < 4; r++) o[nf][r] = 0.f;

    const int nchunks = (q0 + 128) / 64;
    for (int ch = 0; ch < nchunks; ch++) {
        const int kb = ch * 64;
        CP_WAIT0();
        __syncthreads();

        if (ch + 1 < nchunks) {
            const uint32_t ks2 = ksm + ((ch + 1) & 1) * (K_WORDS * 4);
            const uint32_t vs2 = vsm + ((ch + 1) & 1) * (V_WORDS * 4);
            const float* kp = kbase + (size_t)(kb + 64) * HD;
            const float* vp = vbase + (size_t)(kb + 64) * HD;
            #pragma unroll
            for (int i = 0; i < 4; i++) {
                int c = t + i * 256;
                int r = c >> 4, sb = c & 15;
                CP16(ks2 + r * (KSTR*4) + sb * 16, kp + (size_t)r * HD + sb * 4);
                CP16(vs2 + r * (VSTR*4) + sb * 16, vp + (size_t)r * HD + sb * 4);
            }
            CP_COMMIT();
        }

        const uint32_t* Ks = Kb + (ch & 1) * K_WORDS;
        const uint32_t* Vs = Vb + (ch & 1) * V_WORDS;

        float s[8][4];
        #pragma unroll
        for (int nf = 0; nf < 8; nf++)
            #pragma unroll
            for (int r = 0; r < 4; r++) s[nf][r] = 0.f;

        #pragma unroll
        for (int ks = 0; ks < 8; ks++) {
            const int d0 = ks * 8;
            int r = wid * 16 + lr;
            uint32_t a0 = Qs[r * QSTR + d0 + lc];
            uint32_t a1 = Qs[(r + 8) * QSTR + d0 + lc];
            uint32_t a2 = Qs[r * QSTR + d0 + lc + 4];
            uint32_t a3 = Qs[(r + 8) * QSTR + d0 + lc + 4];
            #pragma unroll
            for (int nf = 0; nf < 8; nf++) {
                uint32_t b0 = Ks[(nf * 8 + lr) * KSTR + d0 + lc];
                uint32_t b1 = Ks[(nf * 8 + lr) * KSTR + d0 + lc + 4];
                mma_tf32(s[nf][0], s[nf][1], s[nf][2], s[nf][3],
                         a0, a1, a2, a3, b0, b1);
            }
        }

        if (kb >= q0) {
            int r0 = q0 + wid * 16 + lr, r1 = r0 + 8;
            #pragma unroll
            for (int nf = 0; nf < 8; nf++) {
                int c0 = kb + nf * 8 + 2 * lc, c1 = c0 + 1;
                if (c0 > r0) s[nf][0] = -1e30f;
                if (c1 > r0) s[nf][1] = -1e30f;
                if (c0 > r1) s[nf][2] = -1e30f;
                if (c1 > r1) s[nf][3] = -1e30f;
            }
        }

        float mx0 = -1e30f, mx1 = -1e30f;
        #pragma unroll
        for (int nf = 0; nf < 8; nf++) {
            mx0 = fmaxf(mx0, fmaxf(s[nf][0], s[nf][1]));
            mx1 = fmaxf(mx1, fmaxf(s[nf][2], s[nf][3]));
        }
        #pragma unroll
        for (int off = 1; off < 4; off <<= 1) {
            mx0 = fmaxf(mx0, __shfl_xor_sync(0xffffffffu, mx0, off));
            mx1 = fmaxf(mx1, __shfl_xor_sync(0xffffffffu, mx1, off));
        }
        float mn0 = fmaxf(m0r, mx0), mn1 = fmaxf(m1r, mx1);
        float sc0 = exp2f(m0r - mn0), sc1 = exp2f(m1r - mn1);
        m0r = mn0; m1r = mn1;

        float rs0 = 0.f, rs1 = 0.f;
        const int prow0 = (wid * 16 + lr) * PSTR;
        const int prow1 = prow0 + 8 * PSTR;
        #pragma unroll
        for (int nf = 0; nf < 8; nf++) {
            float p0 = exp2f(s[nf][0] - mn0);
            float p1 = exp2f(s[nf][1] - mn0);
            float p2 = exp2f(s[nf][2] - mn1);
            float p3 = exp2f(s[nf][3] - mn1);
            rs0 += p0 + p1; rs1 += p2 + p3;
            int cofs = nf * 8 + 2 * lc;
            *(uint2*)&Ps[prow0 + cofs] = make_uint2(f2tf(p0), f2tf(p1));
            *(uint2*)&Ps[prow1 + cofs] = make_uint2(f2tf(p2), f2tf(p3));
            o[nf][0] *= sc0; o[nf][1] *= sc0;
            o[nf][2] *= sc1; o[nf][3] *= sc1;
        }
        #pragma unroll
        for (int off = 1; off < 4; off <<= 1) {
            rs0 += __shfl_xor_sync(0xffffffffu, rs0, off);
            rs1 += __shfl_xor_sync(0xffffffffu, rs1, off);
        }
        l0 = l0 * sc0 + rs0;
        l1 = l1 * sc1 + rs1;

        __syncwarp();

        #pragma unroll
        for (int ks = 0; ks < 8; ks++) {
            const int k0 = ks * 8;
            int r = wid * 16 + lr;
            uint32_t a0 = Ps[r * PSTR + k0 + lc];
            uint32_t a1 = Ps[(r + 8) * PSTR + k0 + lc];
            uint32_t a2 = Ps[r * PSTR + k0 + lc + 4];
            uint32_t a3 = Ps[(r + 8) * PSTR + k0 + lc + 4];
            #pragma unroll
            for (int nf = 0; nf < 8; nf++) {
                uint32_t b0 = Vs[(k0 + lc) * VSTR + nf * 8 + lr];
                uint32_t b1 = Vs[(k0 + lc + 4) * VSTR + nf * 8 + lr];
                mma_tf32(o[nf][0], o[nf][1], o[nf][2], o[nf][3],
                         a0, a1, a2, a3, b0, b1);
            }
        }
        __syncthreads();
    }

    const float inv0 = 1.f / l0, inv1 = 1.f / l1;
    const int b = bh >> 4, h = bh & 15;
    const int r0 = q0 + wid * 16 + lr, r1 = r0 + 8;
    #pragma unroll
    for (int nf = 0; nf < 8; nf++) {
        int cb = h * HD + nf * 8 + 2 * lc;
        *(uint2*)&g_ctx[(size_t)(b * SEQ + r0) * DOUT + cb] =
            make_uint2(f2tf(o[nf][0] * inv0), f2tf(o[nf][1] * inv0));
        *(uint2*)&g_ctx[(size_t)(b * SEQ + r1) * DOUT + cb] =
            make_uint2(f2tf(o[nf][2] * inv1), f2tf(o[nf][3] * inv1));
    }
}

// ---------------------------------------------------------------------------
extern "C" void kernel_launch(void* const* d_in, const int* in_sizes, int n_in,
                              void* d_out, int out_size)
{
    const float* x  = (const float*)d_in[0];
    const float* Wq = (const float*)d_in[1];
    const float* Wk = (const float*)d_in[2];
    const float* Wv = (const float*)d_in[3];
    const float* Wo = (const float*)d_in[4];
    const float* bo = (const float*)d_in[5];
    float* out = (float*)d_out;

    cudaFuncSetAttribute(attn_kernel,
                         cudaFuncAttributeMaxDynamicSharedMemorySize, ATTN_SMEM);
    cudaFuncSetAttribute(qkv_gemm,
                         cudaFuncAttributeMaxDynamicSharedMemorySize, GEMM_SMEM);
    cudaFuncSetAttribute(proj_gemm,
                         cudaFuncAttributeMaxDynamicSharedMemorySize, GEMM_SMEM);

    round_w<<<dim3(1024, 4), 256>>>(Wq, Wk, Wv, Wo);
    round_x<<<4096, 256>>>(x);
    qkv_gemm<<<dim3(DOUT / 128, MROWS / 256, 3), 256, GEMM_SMEM>>>();
    attn_kernel<<<dim3(SEQ / 128, BB * NH), 256, ATTN_SMEM>>>();
    proj_gemm<<<dim3(DOUT / 128, MROWS / 256), 256, GEMM_SMEM>>>(bo, out);
}

// round 7
// speedup vs baseline: 5.7672x; 1.0606x over previous
#include <cuda_runtime.h>
#include <cuda_bf16.h>
#include <cstdint>

#define BB   2
#define SEQ  2048
#define DIN  1024
#define DOUT 1024
#define NH   16
#define HD   64
#define MROWS (BB*SEQ)   // 4096

// Scratch (allocation-free requirement -> __device__ globals)
__device__ float g_q[BB*NH*SEQ*HD];    // [B,H,N,HD] tf32-rounded, q pre-scaled by 0.125*log2e
__device__ float g_k[BB*NH*SEQ*HD];
__device__ float g_v[BB*NH*SEQ*HD];
__device__ float g_ctx[MROWS*DOUT];    // [B*N, DOUT] tf32-rounded
__device__ float g_wr[4*DIN*DOUT];     // tf32-rounded weights [K,N] (q,k,v,o)
__device__ float g_xr[MROWS*DIN];      // tf32-rounded x

#define QSCALE 0.1803368801111713f     // 0.125 * log2(e)

// ---------------------------------------------------------------------------
// helpers
// ---------------------------------------------------------------------------
__device__ __forceinline__ uint32_t f2tf(float x) {
    uint32_t u;
    asm("cvt.rna.tf32.f32 %0, %1;" : "=r"(u) : "f"(x));
    return u;
}

__device__ __forceinline__ uint32_t smem_u32(const void* p) {
    uint32_t a;
    asm("{ .reg .u64 t; cvta.to.shared.u64 t, %1; cvt.u32.u64 %0, t; }"
        : "=r"(a) : "l"(p));
    return a;
}

#define CP16(dst, src) \
    asm volatile("cp.async.cg.shared.global [%0], [%1], 16;" \
                 :: "r"(dst), "l"(src) : "memory")
#define CP_COMMIT() asm volatile("cp.async.commit_group;" ::: "memory")
#define CP_WAIT0()  asm volatile("cp.async.wait_group 0;" ::: "memory")

__device__ __forceinline__ void mma_tf32(
    float& c0, float& c1, float& c2, float& c3,
    uint32_t a0, uint32_t a1, uint32_t a2, uint32_t a3,
    uint32_t b0, uint32_t b1)
{
    asm volatile(
        "mma.sync.aligned.m16n8k8.row.col.f32.tf32.tf32.f32 "
        "{%0,%1,%2,%3}, {%4,%5,%6,%7}, {%8,%9}, {%0,%1,%2,%3};\n"
        : "+f"(c0), "+f"(c1), "+f"(c2), "+f"(c3)
        : "r"(a0), "r"(a1), "r"(a2), "r"(a3), "r"(b0), "r"(b1));
}

// ---------------------------------------------------------------------------
// Pre-rounding kernels
// ---------------------------------------------------------------------------
__global__ __launch_bounds__(256) void round_w(
    const float* __restrict__ Wq, const float* __restrict__ Wk,
    const float* __restrict__ Wv, const float* __restrict__ Wo)
{
    const float* src = (blockIdx.y == 0) ? Wq : (blockIdx.y == 1) ? Wk :
                       (blockIdx.y == 2) ? Wv : Wo;
    float* dst = g_wr + ((size_t)blockIdx.y << 20);
    size_t i = ((size_t)blockIdx.x * 256 + threadIdx.x) * 4;
    float4 v = *(const float4*)(src + i);
    *(uint4*)(dst + i) = make_uint4(f2tf(v.x), f2tf(v.y), f2tf(v.z), f2tf(v.w));
}

__global__ __launch_bounds__(256) void round_x(const float* __restrict__ x)
{
    size_t i = ((size_t)blockIdx.x * 256 + threadIdx.x) * 4;
    float4 v = *(const float4*)(x + i);
    *(uint4*)(g_xr + i) = make_uint4(f2tf(v.x), f2tf(v.y), f2tf(v.z), f2tf(v.w));
}

// ---------------------------------------------------------------------------
// cp.async pipelined TF32 HMMA GEMM, tile 256x128x32, 256 thr, 2 stages.
// ---------------------------------------------------------------------------
#define ASTR 36
#define BSTR 136
#define A_BYTES (256 * ASTR * 4)      // 36864
#define B_BYTES (32 * BSTR * 4)       // 17408
#define STAGE_B (A_BYTES + B_BYTES)   // 54272
#define GEMM_SMEM (2 * STAGE_B)       // 108544

struct GemmAcc { float c[4][8][4]; };  // [mf][nf][reg]

__device__ __forceinline__ void gemm_cp_body(
    const float* __restrict__ Ag,
    const float* __restrict__ Bg,
    GemmAcc& acc, char* sm)
{
    const int t    = threadIdx.x;
    const int wid  = t >> 5, lane = t & 31;
    const int lr   = lane >> 2, lc = lane & 3;
    const int wm   = (wid & 3) * 64;
    const int wn   = (wid >> 2) * 64;
    const uint32_t sb0 = smem_u32(sm);

    #pragma unroll
    for (int mf = 0; mf < 4; mf++)
        #pragma unroll
        for (int nf = 0; nf < 8; nf++)
            #pragma unroll
            for (int r = 0; r < 4; r++) acc.c[mf][nf][r] = 0.f;

    uint32_t adst[8], bdst[4];
    const float* asrc[8];
    const float* bsrc[4];
    #pragma unroll
    for (int i = 0; i < 8; i++) {
        int c = t + i * 256;
        int ar = c >> 3, ak = c & 7;
        adst[i] = ar * (ASTR * 4) + ak * 16;
        asrc[i] = Ag + (size_t)ar * 1024 + ak * 4;
    }
    #pragma unroll
    for (int i = 0; i < 4; i++) {
        int c = t + i * 256;
        int br = c >> 5, bn = c & 31;
        bdst[i] = A_BYTES + br * (BSTR * 4) + bn * 16;
        bsrc[i] = Bg + (size_t)br * 1024 + bn * 4;
    }

    #pragma unroll
    for (int i = 0; i < 8; i++) CP16(sb0 + adst[i], asrc[i]);
    #pragma unroll
    for (int i = 0; i < 4; i++) CP16(sb0 + bdst[i], bsrc[i]);
    CP_COMMIT();

    for (int kt = 0; kt < 32; kt++) {
        CP_WAIT0();
        __syncthreads();
        if (kt + 1 < 32) {
            const uint32_t sn = sb0 + ((kt + 1) & 1) * STAGE_B;
            #pragma unroll
            for (int i = 0; i < 8; i++)
                CP16(sn + adst[i], asrc[i] + (kt + 1) * 32);
            #pragma unroll
            for (int i = 0; i < 4; i++)
                CP16(sn + bdst[i], bsrc[i] + (size_t)(kt + 1) * 32 * 1024);
            CP_COMMIT();
        }

        const uint32_t* As = (const uint32_t*)(sm + (kt & 1) * STAGE_B);
        const uint32_t* Bs = (const uint32_t*)(sm + (kt & 1) * STAGE_B + A_BYTES);

        #pragma unroll
        for (int ks = 0; ks < 4; ks++) {
            const int kb = ks * 8;
            uint32_t b[8][2];
            #pragma unroll
            for (int nf = 0; nf < 8; nf++) {
                int c = wn + nf * 8 + lr;
                b[nf][0] = Bs[(kb + lc) * BSTR + c];
                b[nf][1] = Bs[(kb + lc + 4) * BSTR + c];
            }
            #pragma unroll
            for (int mf = 0; mf < 4; mf++) {
                int r = wm + mf * 16 + lr;
                uint32_t a0 = As[r * ASTR + kb + lc];
                uint32_t a1 = As[(r + 8) * ASTR + kb + lc];
                uint32_t a2 = As[r * ASTR + kb + lc + 4];
                uint32_t a3 = As[(r + 8) * ASTR + kb + lc + 4];
                #pragma unroll
                for (int nf = 0; nf < 8; nf++)
                    mma_tf32(acc.c[mf][nf][0], acc.c[mf][nf][1],
                             acc.c[mf][nf][2], acc.c[mf][nf][3],
                             a0, a1, a2, a3, b[nf][0], b[nf][1]);
            }
        }
        __syncthreads();
    }
}

// qkv: z selects weight + destination; writes tf32-rounded (q pre-scaled)
__global__ __launch_bounds__(256, 1) void qkv_gemm()
{
    extern __shared__ char sm[];
    const int m0 = blockIdx.y * 256, n0 = blockIdx.x * 128;
    GemmAcc acc;
    gemm_cp_body(g_xr + (size_t)m0 * DIN,
                 g_wr + ((size_t)blockIdx.z << 20) + n0, acc, sm);

    float* dst = (blockIdx.z == 0) ? g_q : (blockIdx.z == 1) ? g_k : g_v;
    const float qs = (blockIdx.z == 0) ? QSCALE : 1.0f;
    const int t = threadIdx.x, wid = t >> 5, lane = t & 31;
    const int lr = lane >> 2, lc = lane & 3;
    const int wm = (wid & 3) * 64, wn = (wid >> 2) * 64;

    #pragma unroll
    for (int mf = 0; mf < 4; mf++) {
        #pragma unroll
        for (int nf = 0; nf < 8; nf++) {
            int cb = n0 + wn + nf * 8 + 2 * lc;
            int h = cb >> 6, d = cb & 63;
            #pragma unroll
            for (int half = 0; half < 2; half++) {
                int m = m0 + wm + mf * 16 + lr + half * 8;
                int b = m >> 11, n = m & 2047;
                uint2 v = make_uint2(f2tf(acc.c[mf][nf][half*2] * qs),
                                     f2tf(acc.c[mf][nf][half*2+1] * qs));
                *(uint2*)&dst[((size_t)(b * 16 + h) * SEQ + n) * HD + d] = v;
            }
        }
    }
}

// proj: out = ctx @ Wo + bo
__global__ __launch_bounds__(256, 1) void proj_gemm(
    const float* __restrict__ bo, float* __restrict__ out)
{
    extern __shared__ char sm[];
    const int m0 = blockIdx.y * 256, n0 = blockIdx.x * 128;
    GemmAcc acc;
    gemm_cp_body(g_ctx + (size_t)m0 * DOUT,
                 g_wr + ((size_t)3 << 20) + n0, acc, sm);

    const int t = threadIdx.x, wid = t >> 5, lane = t & 31;
    const int lr = lane >> 2, lc = lane & 3;
    const int wm = (wid & 3) * 64, wn = (wid >> 2) * 64;

    #pragma unroll
    for (int mf = 0; mf < 4; mf++) {
        #pragma unroll
        for (int nf = 0; nf < 8; nf++) {
            int cb = n0 + wn + nf * 8 + 2 * lc;
            float2 bias = *(const float2*)&bo[cb];
            #pragma unroll
            for (int half = 0; half < 2; half++) {
                int m = m0 + wm + mf * 16 + lr + half * 8;
                *(float2*)&out[(size_t)m * DOUT + cb] =
                    make_float2(acc.c[mf][nf][half*2] + bias.x,
                                acc.c[mf][nf][half*2+1] + bias.y);
            }
        }
    }
}

// ---------------------------------------------------------------------------
// TF32 flash attention, Q in registers, 2 CTAs/SM.
// Q tile 128 (pre-scaled by 0.125*log2e -> exp2 softmax), K/V chunks 64,
// double-buffered cp.async. Ps is warp-private (each warp touches only its
// own 16 rows) -> single __syncthreads per chunk.
// ---------------------------------------------------------------------------
#define KSTR 68
#define VSTR 72
#define PSTR 68
#define K_WORDS (64*KSTR)
#define V_WORDS (64*VSTR)
#define ATTN_SMEM ((2*K_WORDS + 2*V_WORDS + 128*PSTR) * 4)   // 106496 B

__global__ __launch_bounds__(256, 2) void attn_kernel()
{
    extern __shared__ uint32_t smu[];
    uint32_t* Kb = smu;                          // 2 x [64][KSTR]
    uint32_t* Vb = Kb + 2 * K_WORDS;             // 2 x [64][VSTR]
    uint32_t* Ps = Vb + 2 * V_WORDS;             // [128][PSTR] (Q staging first)

    const int t    = threadIdx.x;
    const int wid  = t >> 5, lane = t & 31;
    const int lr   = lane >> 2, lc = lane & 3;
    const int tile = (gridDim.x - 1) - blockIdx.x;   // heavy tiles first
    const int bh   = blockIdx.y;
    const int q0   = tile * 128;

    const float* qbase = g_q + (size_t)(bh * SEQ + q0) * HD;
    const float* kbase = g_k + (size_t)bh * SEQ * HD;
    const float* vbase = g_v + (size_t)bh * SEQ * HD;

    const uint32_t ksm = smem_u32(Kb);
    const uint32_t vsm = smem_u32(Vb);
    const uint32_t psm = smem_u32(Ps);

    // stage Q into Ps region (coalesced), then lift to registers
    #pragma unroll
    for (int i = 0; i < 8; i++) {
        int c = t + i * 256;
        int r = c >> 4, sb = c & 15;
        CP16(psm + r * (PSTR*4) + sb * 16, qbase + (size_t)r * HD + sb * 4);
    }
    CP_COMMIT();
    // K/V chunk 0
    #pragma unroll
    for (int i = 0; i < 4; i++) {
        int c = t + i * 256;
        int r = c >> 4, sb = c & 15;
        CP16(ksm + r * (KSTR*4) + sb * 16, kbase + (size_t)r * HD + sb * 4);
        CP16(vsm + r * (VSTR*4) + sb * 16, vbase + (size_t)r * HD + sb * 4);
    }
    CP_COMMIT();

    CP_WAIT0();
    __syncthreads();

    // Q fragments -> registers (warp-private rows; conflict-free banks)
    uint32_t qa[8][4];
    {
        const int r = wid * 16 + lr;
        #pragma unroll
        for (int ks = 0; ks < 8; ks++) {
            const int d0 = ks * 8;
            qa[ks][0] = Ps[r * PSTR + d0 + lc];
            qa[ks][1] = Ps[(r + 8) * PSTR + d0 + lc];
            qa[ks][2] = Ps[r * PSTR + d0 + lc + 4];
            qa[ks][3] = Ps[(r + 8) * PSTR + d0 + lc + 4];
        }
    }
    __syncwarp();   // frag reads done before chunk-0 P writes to same rows

    float m0r = -1e30f, m1r = -1e30f, l0 = 0.f, l1 = 0.f;
    float o[8][4];
    #pragma unroll
    for (int nf = 0; nf < 8; nf++)
        #pragma unroll
        for (int r = 0; r < 4; r++) o[nf][r] = 0.f;

    const int nchunks = (q0 + 128) / 64;
    for (int ch = 0; ch < nchunks; ch++) {
        const int kb = ch * 64;
        if (ch > 0) {
            CP_WAIT0();
            __syncthreads();   // chunk data visible + all warps done with prev buffer
        }

        if (ch + 1 < nchunks) {
            const uint32_t ks2 = ksm + ((ch + 1) & 1) * (K_WORDS * 4);
            const uint32_t vs2 = vsm + ((ch + 1) & 1) * (V_WORDS * 4);
            const float* kp = kbase + (size_t)(kb + 64) * HD;
            const float* vp = vbase + (size_t)(kb + 64) * HD;
            #pragma unroll
            for (int i = 0; i < 4; i++) {
                int c = t + i * 256;
                int r = c >> 4, sb = c & 15;
                CP16(ks2 + r * (KSTR*4) + sb * 16, kp + (size_t)r * HD + sb * 4);
                CP16(vs2 + r * (VSTR*4) + sb * 16, vp + (size_t)r * HD + sb * 4);
            }
            CP_COMMIT();
        }

        const uint32_t* Ks = Kb + (ch & 1) * K_WORDS;
        const uint32_t* Vs = Vb + (ch & 1) * V_WORDS;

        // S = Q K^T for this warp's 16 rows x 64 cols
        float s[8][4];
        #pragma unroll
        for (int nf = 0; nf < 8; nf++)
            #pragma unroll
            for (int r = 0; r < 4; r++) s[nf][r] = 0.f;

        #pragma unroll
        for (int ks = 0; ks < 8; ks++) {
            const int d0 = ks * 8;
            #pragma unroll
            for (int nf = 0; nf < 8; nf++) {
                uint32_t b0 = Ks[(nf * 8 + lr) * KSTR + d0 + lc];
                uint32_t b1 = Ks[(nf * 8 + lr) * KSTR + d0 + lc + 4];
                mma_tf32(s[nf][0], s[nf][1], s[nf][2], s[nf][3],
                         qa[ks][0], qa[ks][1], qa[ks][2], qa[ks][3], b0, b1);
            }
        }

        // causal mask (only diagonal chunks)
        if (kb >= q0) {
            int r0 = q0 + wid * 16 + lr, r1 = r0 + 8;
            #pragma unroll
            for (int nf = 0; nf < 8; nf++) {
                int c0 = kb + nf * 8 + 2 * lc, c1 = c0 + 1;
                if (c0 > r0) s[nf][0] = -1e30f;
                if (c1 > r0) s[nf][1] = -1e30f;
                if (c0 > r1) s[nf][2] = -1e30f;
                if (c1 > r1) s[nf][3] = -1e30f;
            }
        }

        // online softmax (base-2; q pre-scaled by 0.125*log2e)
        float mx0 = -1e30f, mx1 = -1e30f;
        #pragma unroll
        for (int nf = 0; nf < 8; nf++) {
            mx0 = fmaxf(mx0, fmaxf(s[nf][0], s[nf][1]));
            mx1 = fmaxf(mx1, fmaxf(s[nf][2], s[nf][3]));
        }
        #pragma unroll
        for (int off = 1; off < 4; off <<= 1) {
            mx0 = fmaxf(mx0, __shfl_xor_sync(0xffffffffu, mx0, off));
            mx1 = fmaxf(mx1, __shfl_xor_sync(0xffffffffu, mx1, off));
        }
        float mn0 = fmaxf(m0r, mx0), mn1 = fmaxf(m1r, mx1);
        float sc0 = exp2f(m0r - mn0), sc1 = exp2f(m1r - mn1);
        m0r = mn0; m1r = mn1;

        float rs0 = 0.f, rs1 = 0.f;
        const int prow0 = (wid * 16 + lr) * PSTR;
        const int prow1 = prow0 + 8 * PSTR;
        #pragma unroll
        for (int nf = 0; nf < 8; nf++) {
            float p0 = exp2f(s[nf][0] - mn0);
            float p1 = exp2f(s[nf][1] - mn0);
            float p2 = exp2f(s[nf][2] - mn1);
            float p3 = exp2f(s[nf][3] - mn1);
            rs0 += p0 + p1; rs1 += p2 + p3;
            int cofs = nf * 8 + 2 * lc;
            *(uint2*)&Ps[prow0 + cofs] = make_uint2(f2tf(p0), f2tf(p1));
            *(uint2*)&Ps[prow1 + cofs] = make_uint2(f2tf(p2), f2tf(p3));
            o[nf][0] *= sc0; o[nf][1] *= sc0;
            o[nf][2] *= sc1; o[nf][3] *= sc1;
        }
        #pragma unroll
        for (int off = 1; off < 4; off <<= 1) {
            rs0 += __shfl_xor_sync(0xffffffffu, rs0, off);
            rs1 += __shfl_xor_sync(0xffffffffu, rs1, off);
        }
        l0 = l0 * sc0 + rs0;
        l1 = l1 * sc1 + rs1;

        __syncwarp();   // P rows are warp-private

        // O += P @ V
        #pragma unroll
        for (int ks = 0; ks < 8; ks++) {
            const int k0 = ks * 8;
            int r = wid * 16 + lr;
            uint32_t a0 = Ps[r * PSTR + k0 + lc];
            uint32_t a1 = Ps[(r + 8) * PSTR + k0 + lc];
            uint32_t a2 = Ps[r * PSTR + k0 + lc + 4];
            uint32_t a3 = Ps[(r + 8) * PSTR + k0 + lc + 4];
            #pragma unroll
            for (int nf = 0; nf < 8; nf++) {
                uint32_t b0 = Vs[(k0 + lc) * VSTR + nf * 8 + lr];
                uint32_t b1 = Vs[(k0 + lc + 4) * VSTR + nf * 8 + lr];
                mma_tf32(o[nf][0], o[nf][1], o[nf][2], o[nf][3],
                         a0, a1, a2, a3, b0, b1);
            }
        }
        __syncwarp();   // P reads done before next chunk's P writes (warp-local)
    }

    const float inv0 = 1.f / l0, inv1 = 1.f / l1;
    const int b = bh >> 4, h = bh & 15;
    const int r0 = q0 + wid * 16 + lr, r1 = r0 + 8;
    #pragma unroll
    for (int nf = 0; nf < 8; nf++) {
        int cb = h * HD + nf * 8 + 2 * lc;
        *(uint2*)&g_ctx[(size_t)(b * SEQ + r0) * DOUT + cb] =
            make_uint2(f2tf(o[nf][0] * inv0), f2tf(o[nf][1] * inv0));
        *(uint2*)&g_ctx[(size_t)(b * SEQ + r1) * DOUT + cb] =
            make_uint2(f2tf(o[nf][2] * inv1), f2tf(o[nf][3] * inv1));
    }
}

// ---------------------------------------------------------------------------
extern "C" void kernel_launch(void* const* d_in, const int* in_sizes, int n_in,
                              void* d_out, int out_size)
{
    const float* x  = (const float*)d_in[0];
    const float* Wq = (const float*)d_in[1];
    const float* Wk = (const float*)d_in[2];
    const float* Wv = (const float*)d_in[3];
    const float* Wo = (const float*)d_in[4];
    const float* bo = (const float*)d_in[5];
    float* out = (float*)d_out;

    cudaFuncSetAttribute(attn_kernel,
                         cudaFuncAttributeMaxDynamicSharedMemorySize, ATTN_SMEM);
    cudaFuncSetAttribute(qkv_gemm,
                         cudaFuncAttributeMaxDynamicSharedMemorySize, GEMM_SMEM);
    cudaFuncSetAttribute(proj_gemm,
                         cudaFuncAttributeMaxDynamicSharedMemorySize, GEMM_SMEM);

    round_w<<<dim3(1024, 4), 256>>>(Wq, Wk, Wv, Wo);
    round_x<<<4096, 256>>>(x);
    qkv_gemm<<<dim3(DOUT / 128, MROWS / 256, 3), 256, GEMM_SMEM>>>();
    attn_kernel<<<dim3(SEQ / 128, BB * NH), 256, ATTN_SMEM>>>();
    proj_gemm<<<dim3(DOUT / 128, MROWS / 256), 256, GEMM_SMEM>>>(bo, out);
}

// round 9
// speedup vs baseline: 6.4726x; 1.1223x over previous
#include <cuda_runtime.h>
#include <cuda_bf16.h>
#include <cstdint>

#define BB   2
#define SEQ  2048
#define DIN  1024
#define DOUT 1024
#define NH   16
#define HD   64
#define MROWS (BB*SEQ)   // 4096
#define NTILE 16         // q-tiles per head
#define NTI   (BB*NH*NTILE)   // 512 tiles

// Scratch (allocation-free requirement -> __device__ globals)
__device__ float g_q[BB*NH*SEQ*HD];    // [B,H,N,HD] tf32-rounded, q pre-scaled by 0.125*log2e
__device__ float g_k[BB*NH*SEQ*HD];
__device__ float g_v[BB*NH*SEQ*HD];
__device__ float g_ctx[MROWS*DOUT];    // [B*N, DOUT] tf32-rounded
__device__ float g_wr[4*DIN*DOUT];     // tf32-rounded weights [K,N] (q,k,v,o)
__device__ float g_xr[MROWS*DIN];      // tf32-rounded x
// split-KV partials
__device__ float g_po[2][NTI*128*64];  // unnormalized O per part
__device__ float g_pm[2][NTI*128];     // running max
__device__ float g_pl[2][NTI*128];     // running sum

#define QSCALE 0.1803368801111713f     // 0.125 * log2(e)

// level -> (tl, part) sorted by per-unit chunk count (tl+1) desc
__constant__ int TL_OF[32] = {15,15,14,14,13,13,12,12,11,11,10,10, 9, 9, 8, 8,
                               7, 7, 6, 6, 5, 5, 4, 4, 3, 3, 2, 2, 1, 1, 0, 0};
__constant__ int PT_OF[32] = { 1, 0, 0, 1, 1, 0, 0, 1, 1, 0, 0, 1, 1, 0, 0, 1,
                               1, 0, 0, 1, 1, 0, 0, 1, 1, 0, 0, 1, 1, 0, 0, 1};

// ---------------------------------------------------------------------------
// helpers
// ---------------------------------------------------------------------------
__device__ __forceinline__ uint32_t f2tf(float x) {
    uint32_t u;
    asm("cvt.rna.tf32.f32 %0, %1;" : "=r"(u) : "f"(x));
    return u;
}

__device__ __forceinline__ uint32_t smem_u32(const void* p) {
    uint32_t a;
    asm("{ .reg .u64 t; cvta.to.shared.u64 t, %1; cvt.u32.u64 %0, t; }"
        : "=r"(a) : "l"(p));
    return a;
}

#define CP16(dst, src) \
    asm volatile("cp.async.cg.shared.global [%0], [%1], 16;" \
                 :: "r"(dst), "l"(src) : "memory")
#define CP_COMMIT() asm volatile("cp.async.commit_group;" ::: "memory")
#define CP_WAIT0()  asm volatile("cp.async.wait_group 0;" ::: "memory")
#define CP_WAIT1()  asm volatile("cp.async.wait_group 1;" ::: "memory")

__device__ __forceinline__ void mma_tf32(
    float& c0, float& c1, float& c2, float& c3,
    uint32_t a0, uint32_t a1, uint32_t a2, uint32_t a3,
    uint32_t b0, uint32_t b1)
{
    asm volatile(
        "mma.sync.aligned.m16n8k8.row.col.f32.tf32.tf32.f32 "
        "{%0,%1,%2,%3}, {%4,%5,%6,%7}, {%8,%9}, {%0,%1,%2,%3};\n"
        : "+f"(c0), "+f"(c1), "+f"(c2), "+f"(c3)
        : "r"(a0), "r"(a1), "r"(a2), "r"(a3), "r"(b0), "r"(b1));
}

// ---------------------------------------------------------------------------
// Pre-rounding kernels
// ---------------------------------------------------------------------------
__global__ __launch_bounds__(256) void round_w(
    const float* __restrict__ Wq, const float* __restrict__ Wk,
    const float* __restrict__ Wv, const float* __restrict__ Wo)
{
    const float* src = (blockIdx.y == 0) ? Wq : (blockIdx.y == 1) ? Wk :
                       (blockIdx.y == 2) ? Wv : Wo;
    float* dst = g_wr + ((size_t)blockIdx.y << 20);
    size_t i = ((size_t)blockIdx.x * 256 + threadIdx.x) * 4;
    float4 v = *(const float4*)(src + i);
    *(uint4*)(dst + i) = make_uint4(f2tf(v.x), f2tf(v.y), f2tf(v.z), f2tf(v.w));
}

__global__ __launch_bounds__(256) void round_x(const float* __restrict__ x)
{
    size_t i = ((size_t)blockIdx.x * 256 + threadIdx.x) * 4;
    float4 v = *(const float4*)(x + i);
    *(uint4*)(g_xr + i) = make_uint4(f2tf(v.x), f2tf(v.y), f2tf(v.z), f2tf(v.w));
}

// ---------------------------------------------------------------------------
// cp.async pipelined TF32 HMMA GEMM, tile 256x128x32, 256 thr, 3 stages.
// ---------------------------------------------------------------------------
#define ASTR 36
#define BSTR 136
#define A_BYTES (256 * ASTR * 4)      // 36864
#define B_BYTES (32 * BSTR * 4)       // 17408
#define STAGE_B (A_BYTES + B_BYTES)   // 54272
#define GEMM_SMEM (3 * STAGE_B)       // 162816

struct GemmAcc { float c[4][8][4]; };  // [mf][nf][reg]

__device__ __forceinline__ void gemm_cp_body(
    const float* __restrict__ Ag,
    const float* __restrict__ Bg,
    GemmAcc& acc, char* sm)
{
    const int t    = threadIdx.x;
    const int wid  = t >> 5, lane = t & 31;
    const int lr   = lane >> 2, lc = lane & 3;
    const int wm   = (wid & 3) * 64;
    const int wn   = (wid >> 2) * 64;
    const uint32_t sb0 = smem_u32(sm);

    #pragma unroll
    for (int mf = 0; mf < 4; mf++)
        #pragma unroll
        for (int nf = 0; nf < 8; nf++)
            #pragma unroll
            for (int r = 0; r < 4; r++) acc.c[mf][nf][r] = 0.f;

    uint32_t adst[8], bdst[4];
    const float* asrc[8];
    const float* bsrc[4];
    #pragma unroll
    for (int i = 0; i < 8; i++) {
        int c = t + i * 256;
        int ar = c >> 3, ak = c & 7;
        adst[i] = ar * (ASTR * 4) + ak * 16;
        asrc[i] = Ag + (size_t)ar * 1024 + ak * 4;
    }
    #pragma unroll
    for (int i = 0; i < 4; i++) {
        int c = t + i * 256;
        int br = c >> 5, bn = c & 31;
        bdst[i] = A_BYTES + br * (BSTR * 4) + bn * 16;
        bsrc[i] = Bg + (size_t)br * 1024 + bn * 4;
    }

    // prologue: stages 0 and 1
    #pragma unroll
    for (int i = 0; i < 8; i++) CP16(sb0 + adst[i], asrc[i]);
    #pragma unroll
    for (int i = 0; i < 4; i++) CP16(sb0 + bdst[i], bsrc[i]);
    CP_COMMIT();
    {
        const uint32_t sn = sb0 + STAGE_B;
        #pragma unroll
        for (int i = 0; i < 8; i++) CP16(sn + adst[i], asrc[i] + 32);
        #pragma unroll
        for (int i = 0; i < 4; i++) CP16(sn + bdst[i], bsrc[i] + (size_t)32 * 1024);
        CP_COMMIT();
    }

    for (int kt = 0; kt < 32; kt++) {
        if (kt < 31) CP_WAIT1(); else CP_WAIT0();
        __syncthreads();   // kt data visible; everyone done with kt-1's buffer
        if (kt + 2 < 32) {
            const uint32_t sn = sb0 + ((kt + 2) % 3) * STAGE_B;
            #pragma unroll
            for (int i = 0; i < 8; i++)
                CP16(sn + adst[i], asrc[i] + (kt + 2) * 32);
            #pragma unroll
            for (int i = 0; i < 4; i++)
                CP16(sn + bdst[i], bsrc[i] + (size_t)(kt + 2) * 32 * 1024);
            CP_COMMIT();
        }

        const uint32_t* As = (const uint32_t*)(sm + (kt % 3) * STAGE_B);
        const uint32_t* Bs = (const uint32_t*)(sm + (kt % 3) * STAGE_B + A_BYTES);

        #pragma unroll
        for (int ks = 0; ks < 4; ks++) {
            const int kb = ks * 8;
            uint32_t b[8][2];
            #pragma unroll
            for (int nf = 0; nf < 8; nf++) {
                int c = wn + nf * 8 + lr;
                b[nf][0] = Bs[(kb + lc) * BSTR + c];
                b[nf][1] = Bs[(kb + lc + 4) * BSTR + c];
            }
            #pragma unroll
            for (int mf = 0; mf < 4; mf++) {
                int r = wm + mf * 16 + lr;
                uint32_t a0 = As[r * ASTR + kb + lc];
                uint32_t a1 = As[(r + 8) * ASTR + kb + lc];
                uint32_t a2 = As[r * ASTR + kb + lc + 4];
                uint32_t a3 = As[(r + 8) * ASTR + kb + lc + 4];
                #pragma unroll
                for (int nf = 0; nf < 8; nf++)
                    mma_tf32(acc.c[mf][nf][0], acc.c[mf][nf][1],
                             acc.c[mf][nf][2], acc.c[mf][nf][3],
                             a0, a1, a2, a3, b[nf][0], b[nf][1]);
            }
        }
    }
}

// qkv: z selects weight + destination; writes tf32-rounded (q pre-scaled)
__global__ __launch_bounds__(256, 1) void qkv_gemm()
{
    extern __shared__ char sm[];
    const int m0 = blockIdx.y * 256, n0 = blockIdx.x * 128;
    GemmAcc acc;
    gemm_cp_body(g_xr + (size_t)m0 * DIN,
                 g_wr + ((size_t)blockIdx.z << 20) + n0, acc, sm);

    float* dst = (blockIdx.z == 0) ? g_q : (blockIdx.z == 1) ? g_k : g_v;
    const float qs = (blockIdx.z == 0) ? QSCALE : 1.0f;
    const int t = threadIdx.x, wid = t >> 5, lane = t & 31;
    const int lr = lane >> 2, lc = lane & 3;
    const int wm = (wid & 3) * 64, wn = (wid >> 2) * 64;

    #pragma unroll
    for (int mf = 0; mf < 4; mf++) {
        #pragma unroll
        for (int nf = 0; nf < 8; nf++) {
            int cb = n0 + wn + nf * 8 + 2 * lc;
            int h = cb >> 6, d = cb & 63;
            #pragma unroll
            for (int half = 0; half < 2; half++) {
                int m = m0 + wm + mf * 16 + lr + half * 8;
                int b = m >> 11, n = m & 2047;
                uint2 v = make_uint2(f2tf(acc.c[mf][nf][half*2] * qs),
                                     f2tf(acc.c[mf][nf][half*2+1] * qs));
                *(uint2*)&dst[((size_t)(b * 16 + h) * SEQ + n) * HD + d] = v;
            }
        }
    }
}

// proj: out = ctx @ Wo + bo
__global__ __launch_bounds__(256, 1) void proj_gemm(
    const float* __restrict__ bo, float* __restrict__ out)
{
    extern __shared__ char sm[];
    const int m0 = blockIdx.y * 256, n0 = blockIdx.x * 128;
    GemmAcc acc;
    gemm_cp_body(g_ctx + (size_t)m0 * DOUT,
                 g_wr + ((size_t)3 << 20) + n0, acc, sm);

    const int t = threadIdx.x, wid = t >> 5, lane = t & 31;
    const int lr = lane >> 2, lc = lane & 3;
    const int wm = (wid & 3) * 64, wn = (wid >> 2) * 64;

    #pragma unroll
    for (int mf = 0; mf < 4; mf++) {
        #pragma unroll
        for (int nf = 0; nf < 8; nf++) {
            int cb = n0 + wn + nf * 8 + 2 * lc;
            float2 bias = *(const float2*)&bo[cb];
            #pragma unroll
            for (int half = 0; half < 2; half++) {
                int m = m0 + wm + mf * 16 + lr + half * 8;
                *(float2*)&out[(size_t)m * DOUT + cb] =
                    make_float2(acc.c[mf][nf][half*2] + bias.x,
                                acc.c[mf][nf][half*2+1] + bias.y);
            }
        }
    }
}

// ---------------------------------------------------------------------------
// Split-KV TF32 flash attention. Each unit = (tile, half-of-keys).
// Tile tl has C = 2*tl+2 chunks; each part handles tl+1 of them.
// grid 1024 (32 levels x 32 bh), heaviest levels first. Writes partials.
// ---------------------------------------------------------------------------
#define KSTR 68
#define VSTR 72
#define PSTR 68
#define K_WORDS (64*KSTR)
#define V_WORDS (64*VSTR)
#define ATTN_SMEM ((2*K_WORDS + 2*V_WORDS + 128*PSTR) * 4)   // 106496 B

__global__ __launch_bounds__(256, 2) void attn_kernel()
{
    extern __shared__ uint32_t smu[];
    uint32_t* Kb = smu;                          // 2 x [64][KSTR]
    uint32_t* Vb = Kb + 2 * K_WORDS;             // 2 x [64][VSTR]
    uint32_t* Ps = Vb + 2 * V_WORDS;             // [128][PSTR] (Q staging first)

    const int t    = threadIdx.x;
    const int wid  = t >> 5, lane = t & 31;
    const int lr   = lane >> 2, lc = lane & 3;

    const int u    = blockIdx.x;
    const int lvl  = u >> 5, bh = u & 31;
    const int tl   = TL_OF[lvl];
    const int part = PT_OF[lvl];
    const int C    = 2 * tl + 2;        // FIXED: full key coverage
    const int Ah   = tl + 1;            // half split
    const int c0   = part ? Ah : 0;
    const int c1   = part ? C  : Ah;
    const int q0   = tl * 128;
    const int ti   = bh * NTILE + tl;

    const float* qbase = g_q + (size_t)(bh * SEQ + q0) * HD;
    const float* kbase = g_k + (size_t)bh * SEQ * HD;
    const float* vbase = g_v + (size_t)bh * SEQ * HD;

    const uint32_t ksm = smem_u32(Kb);
    const uint32_t vsm = smem_u32(Vb);
    const uint32_t psm = smem_u32(Ps);

    // stage Q into Ps region (coalesced), then lift to registers
    #pragma unroll
    for (int i = 0; i < 8; i++) {
        int c = t + i * 256;
        int r = c >> 4, sb = c & 15;
        CP16(psm + r * (PSTR*4) + sb * 16, qbase + (size_t)r * HD + sb * 4);
    }
    CP_COMMIT();
    // first K/V chunk (c0)
    {
        const float* kp = kbase + (size_t)c0 * 64 * HD;
        const float* vp = vbase + (size_t)c0 * 64 * HD;
        const uint32_t ks2 = ksm + (c0 & 1) * (K_WORDS * 4);
        const uint32_t vs2 = vsm + (c0 & 1) * (V_WORDS * 4);
        #pragma unroll
        for (int i = 0; i < 4; i++) {
            int c = t + i * 256;
            int r = c >> 4, sb = c & 15;
            CP16(ks2 + r * (KSTR*4) + sb * 16, kp + (size_t)r * HD + sb * 4);
            CP16(vs2 + r * (VSTR*4) + sb * 16, vp + (size_t)r * HD + sb * 4);
        }
        CP_COMMIT();
    }

    CP_WAIT0();
    __syncthreads();

    // Q fragments -> registers
    uint32_t qa[8][4];
    {
        const int r = wid * 16 + lr;
        #pragma unroll
        for (int ks = 0; ks < 8; ks++) {
            const int d0 = ks * 8;
            qa[ks][0] = Ps[r * PSTR + d0 + lc];
            qa[ks][1] = Ps[(r + 8) * PSTR + d0 + lc];
            qa[ks][2] = Ps[r * PSTR + d0 + lc + 4];
            qa[ks][3] = Ps[(r + 8) * PSTR + d0 + lc + 4];
        }
    }
    __syncwarp();

    float m0r = -1e30f, m1r = -1e30f, l0 = 0.f, l1 = 0.f;
    float o[8][4];
    #pragma unroll
    for (int nf = 0; nf < 8; nf++)
        #pragma unroll
        for (int r = 0; r < 4; r++) o[nf][r] = 0.f;

    for (int ch = c0; ch < c1; ch++) {
        const int kb = ch * 64;
        if (ch > c0) {
            CP_WAIT0();
            __syncthreads();
        }

        if (ch + 1 < c1) {
            const uint32_t ks2 = ksm + ((ch + 1) & 1) * (K_WORDS * 4);
            const uint32_t vs2 = vsm + ((ch + 1) & 1) * (V_WORDS * 4);
            const float* kp = kbase + (size_t)(kb + 64) * HD;
            const float* vp = vbase + (size_t)(kb + 64) * HD;
            #pragma unroll
            for (int i = 0; i < 4; i++) {
                int c = t + i * 256;
                int r = c >> 4, sb = c & 15;
                CP16(ks2 + r * (KSTR*4) + sb * 16, kp + (size_t)r * HD + sb * 4);
                CP16(vs2 + r * (VSTR*4) + sb * 16, vp + (size_t)r * HD + sb * 4);
            }
            CP_COMMIT();
        }

        const uint32_t* Ks = Kb + (ch & 1) * K_WORDS;
        const uint32_t* Vs = Vb + (ch & 1) * V_WORDS;

        float s[8][4];
        #pragma unroll
        for (int nf = 0; nf < 8; nf++)
            #pragma unroll
            for (int r = 0; r < 4; r++) s[nf][r] = 0.f;

        #pragma unroll
        for (int ks = 0; ks < 8; ks++) {
            const int d0 = ks * 8;
            #pragma unroll
            for (int nf = 0; nf < 8; nf++) {
                uint32_t b0 = Ks[(nf * 8 + lr) * KSTR + d0 + lc];
                uint32_t b1 = Ks[(nf * 8 + lr) * KSTR + d0 + lc + 4];
                mma_tf32(s[nf][0], s[nf][1], s[nf][2], s[nf][3],
                         qa[ks][0], qa[ks][1], qa[ks][2], qa[ks][3], b0, b1);
            }
        }

        if (kb >= q0) {
            int r0 = q0 + wid * 16 + lr, r1 = r0 + 8;
            #pragma unroll
            for (int nf = 0; nf < 8; nf++) {
                int cc0 = kb + nf * 8 + 2 * lc, cc1 = cc0 + 1;
                if (cc0 > r0) s[nf][0] = -1e30f;
                if (cc1 > r0) s[nf][1] = -1e30f;
                if (cc0 > r1) s[nf][2] = -1e30f;
                if (cc1 > r1) s[nf][3] = -1e30f;
            }
        }

        float mx0 = -1e30f, mx1 = -1e30f;
        #pragma unroll
        for (int nf = 0; nf < 8; nf++) {
            mx0 = fmaxf(mx0, fmaxf(s[nf][0], s[nf][1]));
            mx1 = fmaxf(mx1, fmaxf(s[nf][2], s[nf][3]));
        }
        #pragma unroll
        for (int off = 1; off < 4; off <<= 1) {
            mx0 = fmaxf(mx0, __shfl_xor_sync(0xffffffffu, mx0, off));
            mx1 = fmaxf(mx1, __shfl_xor_sync(0xffffffffu, mx1, off));
        }
        float mn0 = fmaxf(m0r, mx0), mn1 = fmaxf(m1r, mx1);
        float sc0 = exp2f(m0r - mn0), sc1 = exp2f(m1r - mn1);
        m0r = mn0; m1r = mn1;

        float rs0 = 0.f, rs1 = 0.f;
        const int prow0 = (wid * 16 + lr) * PSTR;
        const int prow1 = prow0 + 8 * PSTR;
        #pragma unroll
        for (int nf = 0; nf < 8; nf++) {
            float p0 = exp2f(s[nf][0] - mn0);
            float p1 = exp2f(s[nf][1] - mn0);
            float p2 = exp2f(s[nf][2] - mn1);
            float p3 = exp2f(s[nf][3] - mn1);
            rs0 += p0 + p1; rs1 += p2 + p3;
            int cofs = nf * 8 + 2 * lc;
            *(uint2*)&Ps[prow0 + cofs] = make_uint2(f2tf(p0), f2tf(p1));
            *(uint2*)&Ps[prow1 + cofs] = make_uint2(f2tf(p2), f2tf(p3));
            o[nf][0] *= sc0; o[nf][1] *= sc0;
            o[nf][2] *= sc1; o[nf][3] *= sc1;
        }
        #pragma unroll
        for (int off = 1; off < 4; off <<= 1) {
            rs0 += __shfl_xor_sync(0xffffffffu, rs0, off);
            rs1 += __shfl_xor_sync(0xffffffffu, rs1, off);
        }
        l0 = l0 * sc0 + rs0;
        l1 = l1 * sc1 + rs1;

        __syncwarp();

        #pragma unroll
        for (int ks = 0; ks < 8; ks++) {
            const int k0 = ks * 8;
            int r = wid * 16 + lr;
            uint32_t a0 = Ps[r * PSTR + k0 + lc];
            uint32_t a1 = Ps[(r + 8) * PSTR + k0 + lc];
            uint32_t a2 = Ps[r * PSTR + k0 + lc + 4];
            uint32_t a3 = Ps[(r + 8) * PSTR + k0 + lc + 4];
            #pragma unroll
            for (int nf = 0; nf < 8; nf++) {
                uint32_t b0 = Vs[(k0 + lc) * VSTR + nf * 8 + lr];
                uint32_t b1 = Vs[(k0 + lc + 4) * VSTR + nf * 8 + lr];
                mma_tf32(o[nf][0], o[nf][1], o[nf][2], o[nf][3],
                         a0, a1, a2, a3, b0, b1);
            }
        }
        __syncwarp();
    }

    // write partials (unnormalized o; per-row m, l)
    const int r0 = wid * 16 + lr, r1 = r0 + 8;
    float* po = g_po[part];
    #pragma unroll
    for (int nf = 0; nf < 8; nf++) {
        int cb = nf * 8 + 2 * lc;
        *(float2*)&po[((size_t)ti * 128 + r0) * 64 + cb] = make_float2(o[nf][0], o[nf][1]);
        *(float2*)&po[((size_t)ti * 128 + r1) * 64 + cb] = make_float2(o[nf][2], o[nf][3]);
    }
    if (lc == 0) {
        g_pm[part][ti * 128 + r0] = m0r;
        g_pm[part][ti * 128 + r1] = m1r;
        g_pl[part][ti * 128 + r0] = l0;
        g_pl[part][ti * 128 + r1] = l1;
    }
}

// ---------------------------------------------------------------------------
// Merge partials -> g_ctx (tf32-rounded). grid 512, block 256.
// Thread handles half a row (32 cols).
// ---------------------------------------------------------------------------
__global__ __launch_bounds__(256) void merge_attn()
{
    const int ti = blockIdx.x, t = threadIdx.x;
    const int r = t >> 1, hh = t & 1;
    const int bh = ti >> 4, tl = ti & 15;
    const int b = bh >> 4, h = bh & 15;
    const int grow = tl * 128 + r;

    const int ri = ti * 128 + r;
    float ma = g_pm[0][ri], mb = g_pm[1][ri];
    float la = g_pl[0][ri], lb = g_pl[1][ri];
    float M  = fmaxf(ma, mb);
    float wa = exp2f(ma - M), wb = exp2f(mb - M);
    float inv = 1.f / (la * wa + lb * wb);
    wa *= inv; wb *= inv;

    const float4* pa = (const float4*)&g_po[0][((size_t)ri) * 64 + hh * 32];
    const float4* pb = (const float4*)&g_po[1][((size_t)ri) * 64 + hh * 32];
    uint4* dst = (uint4*)&g_ctx[(size_t)(b * SEQ + grow) * DOUT + h * HD + hh * 32];

    #pragma unroll
    for (int i = 0; i < 8; i++) {
        float4 va = pa[i], vb = pb[i];
        dst[i] = make_uint4(f2tf(va.x * wa + vb.x * wb),
                            f2tf(va.y * wa + vb.y * wb),
                            f2tf(va.z * wa + vb.z * wb),
                            f2tf(va.w * wa + vb.w * wb));
    }
}

// ---------------------------------------------------------------------------
extern "C" void kernel_launch(void* const* d_in, const int* in_sizes, int n_in,
                              void* d_out, int out_size)
{
    const float* x  = (const float*)d_in[0];
    const float* Wq = (const float*)d_in[1];
    const float* Wk = (const float*)d_in[2];
    const float* Wv = (const float*)d_in[3];
    const float* Wo = (const float*)d_in[4];
    const float* bo = (const float*)d_in[5];
    float* out = (float*)d_out;

    cudaFuncSetAttribute(attn_kernel,
                         cudaFuncAttributeMaxDynamicSharedMemorySize, ATTN_SMEM);
    cudaFuncSetAttribute(qkv_gemm,
                         cudaFuncAttributeMaxDynamicSharedMemorySize, GEMM_SMEM);
    cudaFuncSetAttribute(proj_gemm,
                         cudaFuncAttributeMaxDynamicSharedMemorySize, GEMM_SMEM);

    round_w<<<dim3(1024, 4), 256>>>(Wq, Wk, Wv, Wo);
    round_x<<<4096, 256>>>(x);
    qkv_gemm<<<dim3(DOUT / 128, MROWS / 256, 3), 256, GEMM_SMEM>>>();
    attn_kernel<<<1024, 256, ATTN_SMEM>>>();
    merge_attn<<<NTI, 256>>>();
    proj_gemm<<<dim3(DOUT / 128, MROWS / 256), 256, GEMM_SMEM>>>(bo, out);
}

// round 10
// speedup vs baseline: 6.6910x; 1.0338x over previous
#include <cuda_runtime.h>
#include <cuda_bf16.h>
#include <cstdint>

#define BB   2
#define SEQ  2048
#define DIN  1024
#define DOUT 1024
#define NH   16
#define HD   64
#define MROWS (BB*SEQ)   // 4096
#define NTILE 16         // q-tiles per head
#define NTI   (BB*NH*NTILE)   // 512 tiles

// Scratch (allocation-free requirement -> __device__ globals)
__device__ float g_q[BB*NH*SEQ*HD];    // [B,H,N,HD] tf32-rounded, q pre-scaled by 0.125*log2e
__device__ float g_k[BB*NH*SEQ*HD];
__device__ float g_v[BB*NH*SEQ*HD];
__device__ float g_ctx[MROWS*DOUT];    // [B*N, DOUT] tf32-rounded
__device__ float g_wr[4*DIN*DOUT];     // tf32-rounded weights [K,N] (q,k,v,o)
__device__ float g_xr[MROWS*DIN];      // tf32-rounded x
// split-KV partials
__device__ float g_po[2][NTI*128*64];  // unnormalized O per part
__device__ float g_pm[2][NTI*128];     // running max
__device__ float g_pl[2][NTI*128];     // running sum

#define QSCALE 0.1803368801111713f     // 0.125 * log2(e)

// level -> (tl, part) sorted by per-unit chunk count (tl+1) desc
__constant__ int TL_OF[32] = {15,15,14,14,13,13,12,12,11,11,10,10, 9, 9, 8, 8,
                               7, 7, 6, 6, 5, 5, 4, 4, 3, 3, 2, 2, 1, 1, 0, 0};
__constant__ int PT_OF[32] = { 1, 0, 0, 1, 1, 0, 0, 1, 1, 0, 0, 1, 1, 0, 0, 1,
                               1, 0, 0, 1, 1, 0, 0, 1, 1, 0, 0, 1, 1, 0, 0, 1};

// ---------------------------------------------------------------------------
// helpers
// ---------------------------------------------------------------------------
__device__ __forceinline__ uint32_t f2tf(float x) {
    uint32_t u;
    asm("cvt.rna.tf32.f32 %0, %1;" : "=r"(u) : "f"(x));
    return u;
}

__device__ __forceinline__ uint32_t smem_u32(const void* p) {
    uint32_t a;
    asm("{ .reg .u64 t; cvta.to.shared.u64 t, %1; cvt.u32.u64 %0, t; }"
        : "=r"(a) : "l"(p));
    return a;
}

#define CP16(dst, src) \
    asm volatile("cp.async.cg.shared.global [%0], [%1], 16;" \
                 :: "r"(dst), "l"(src) : "memory")
#define CP_COMMIT() asm volatile("cp.async.commit_group;" ::: "memory")
#define CP_WAIT0()  asm volatile("cp.async.wait_group 0;" ::: "memory")
#define CP_WAIT1()  asm volatile("cp.async.wait_group 1;" ::: "memory")
#define CP_WAIT2()  asm volatile("cp.async.wait_group 2;" ::: "memory")

__device__ __forceinline__ void mma_tf32(
    float& c0, float& c1, float& c2, float& c3,
    uint32_t a0, uint32_t a1, uint32_t a2, uint32_t a3,
    uint32_t b0, uint32_t b1)
{
    asm volatile(
        "mma.sync.aligned.m16n8k8.row.col.f32.tf32.tf32.f32 "
        "{%0,%1,%2,%3}, {%4,%5,%6,%7}, {%8,%9}, {%0,%1,%2,%3};\n"
        : "+f"(c0), "+f"(c1), "+f"(c2), "+f"(c3)
        : "r"(a0), "r"(a1), "r"(a2), "r"(a3), "r"(b0), "r"(b1));
}

// ---------------------------------------------------------------------------
// Pre-rounding kernels
// ---------------------------------------------------------------------------
__global__ __launch_bounds__(256) void round_w(
    const float* __restrict__ Wq, const float* __restrict__ Wk,
    const float* __restrict__ Wv, const float* __restrict__ Wo)
{
    const float* src = (blockIdx.y == 0) ? Wq : (blockIdx.y == 1) ? Wk :
                       (blockIdx.y == 2) ? Wv : Wo;
    float* dst = g_wr + ((size_t)blockIdx.y << 20);
    size_t i = ((size_t)blockIdx.x * 256 + threadIdx.x) * 4;
    float4 v = *(const float4*)(src + i);
    *(uint4*)(dst + i) = make_uint4(f2tf(v.x), f2tf(v.y), f2tf(v.z), f2tf(v.w));
}

__global__ __launch_bounds__(256) void round_x(const float* __restrict__ x)
{
    size_t i = ((size_t)blockIdx.x * 256 + threadIdx.x) * 4;
    float4 v = *(const float4*)(x + i);
    *(uint4*)(g_xr + i) = make_uint4(f2tf(v.x), f2tf(v.y), f2tf(v.z), f2tf(v.w));
}

// ---------------------------------------------------------------------------
// cp.async pipelined TF32 HMMA GEMM, tile 256x128x32, 256 thr, 3 stages.
// ---------------------------------------------------------------------------
#define ASTR 36
#define BSTR 136
#define A_BYTES (256 * ASTR * 4)      // 36864
#define B_BYTES (32 * BSTR * 4)       // 17408
#define STAGE_B (A_BYTES + B_BYTES)   // 54272
#define GEMM_SMEM (3 * STAGE_B)       // 162816

struct GemmAcc { float c[4][8][4]; };  // [mf][nf][reg]

__device__ __forceinline__ void gemm_cp_body(
    const float* __restrict__ Ag,
    const float* __restrict__ Bg,
    GemmAcc& acc, char* sm)
{
    const int t    = threadIdx.x;
    const int wid  = t >> 5, lane = t & 31;
    const int lr   = lane >> 2, lc = lane & 3;
    const int wm   = (wid & 3) * 64;
    const int wn   = (wid >> 2) * 64;
    const uint32_t sb0 = smem_u32(sm);

    #pragma unroll
    for (int mf = 0; mf < 4; mf++)
        #pragma unroll
        for (int nf = 0; nf < 8; nf++)
            #pragma unroll
            for (int r = 0; r < 4; r++) acc.c[mf][nf][r] = 0.f;

    uint32_t adst[8], bdst[4];
    const float* asrc[8];
    const float* bsrc[4];
    #pragma unroll
    for (int i = 0; i < 8; i++) {
        int c = t + i * 256;
        int ar = c >> 3, ak = c & 7;
        adst[i] = ar * (ASTR * 4) + ak * 16;
        asrc[i] = Ag + (size_t)ar * 1024 + ak * 4;
    }
    #pragma unroll
    for (int i = 0; i < 4; i++) {
        int c = t + i * 256;
        int br = c >> 5, bn = c & 31;
        bdst[i] = A_BYTES + br * (BSTR * 4) + bn * 16;
        bsrc[i] = Bg + (size_t)br * 1024 + bn * 4;
    }

    // prologue: stages 0 and 1
    #pragma unroll
    for (int i = 0; i < 8; i++) CP16(sb0 + adst[i], asrc[i]);
    #pragma unroll
    for (int i = 0; i < 4; i++) CP16(sb0 + bdst[i], bsrc[i]);
    CP_COMMIT();
    {
        const uint32_t sn = sb0 + STAGE_B;
        #pragma unroll
        for (int i = 0; i < 8; i++) CP16(sn + adst[i], asrc[i] + 32);
        #pragma unroll
        for (int i = 0; i < 4; i++) CP16(sn + bdst[i], bsrc[i] + (size_t)32 * 1024);
        CP_COMMIT();
    }

    for (int kt = 0; kt < 32; kt++) {
        if (kt < 31) CP_WAIT1(); else CP_WAIT0();
        __syncthreads();   // kt data visible; everyone done with kt-1's buffer
        if (kt + 2 < 32) {
            const uint32_t sn = sb0 + ((kt + 2) % 3) * STAGE_B;
            #pragma unroll
            for (int i = 0; i < 8; i++)
                CP16(sn + adst[i], asrc[i] + (kt + 2) * 32);
            #pragma unroll
            for (int i = 0; i < 4; i++)
                CP16(sn + bdst[i], bsrc[i] + (size_t)(kt + 2) * 32 * 1024);
            CP_COMMIT();
        }

        const uint32_t* As = (const uint32_t*)(sm + (kt % 3) * STAGE_B);
        const uint32_t* Bs = (const uint32_t*)(sm + (kt % 3) * STAGE_B + A_BYTES);

        #pragma unroll
        for (int ks = 0; ks < 4; ks++) {
            const int kb = ks * 8;
            uint32_t b[8][2];
            #pragma unroll
            for (int nf = 0; nf < 8; nf++) {
                int c = wn + nf * 8 + lr;
                b[nf][0] = Bs[(kb + lc) * BSTR + c];
                b[nf][1] = Bs[(kb + lc + 4) * BSTR + c];
            }
            #pragma unroll
            for (int mf = 0; mf < 4; mf++) {
                int r = wm + mf * 16 + lr;
                uint32_t a0 = As[r * ASTR + kb + lc];
                uint32_t a1 = As[(r + 8) * ASTR + kb + lc];
                uint32_t a2 = As[r * ASTR + kb + lc + 4];
                uint32_t a3 = As[(r + 8) * ASTR + kb + lc + 4];
                #pragma unroll
                for (int nf = 0; nf < 8; nf++)
                    mma_tf32(acc.c[mf][nf][0], acc.c[mf][nf][1],
                             acc.c[mf][nf][2], acc.c[mf][nf][3],
                             a0, a1, a2, a3, b[nf][0], b[nf][1]);
            }
        }
    }
}

// qkv: z selects weight + destination; writes tf32-rounded (q pre-scaled)
__global__ __launch_bounds__(256, 1) void qkv_gemm()
{
    extern __shared__ char sm[];
    const int m0 = blockIdx.y * 256, n0 = blockIdx.x * 128;
    GemmAcc acc;
    gemm_cp_body(g_xr + (size_t)m0 * DIN,
                 g_wr + ((size_t)blockIdx.z << 20) + n0, acc, sm);

    float* dst = (blockIdx.z == 0) ? g_q : (blockIdx.z == 1) ? g_k : g_v;
    const float qs = (blockIdx.z == 0) ? QSCALE : 1.0f;
    const int t = threadIdx.x, wid = t >> 5, lane = t & 31;
    const int lr = lane >> 2, lc = lane & 3;
    const int wm = (wid & 3) * 64, wn = (wid >> 2) * 64;

    #pragma unroll
    for (int mf = 0; mf < 4; mf++) {
        #pragma unroll
        for (int nf = 0; nf < 8; nf++) {
            int cb = n0 + wn + nf * 8 + 2 * lc;
            int h = cb >> 6, d = cb & 63;
            #pragma unroll
            for (int half = 0; half < 2; half++) {
                int m = m0 + wm + mf * 16 + lr + half * 8;
                int b = m >> 11, n = m & 2047;
                uint2 v = make_uint2(f2tf(acc.c[mf][nf][half*2] * qs),
                                     f2tf(acc.c[mf][nf][half*2+1] * qs));
                *(uint2*)&dst[((size_t)(b * 16 + h) * SEQ + n) * HD + d] = v;
            }
        }
    }
}

// proj: out = ctx @ Wo + bo
__global__ __launch_bounds__(256, 1) void proj_gemm(
    const float* __restrict__ bo, float* __restrict__ out)
{
    extern __shared__ char sm[];
    const int m0 = blockIdx.y * 256, n0 = blockIdx.x * 128;
    GemmAcc acc;
    gemm_cp_body(g_ctx + (size_t)m0 * DOUT,
                 g_wr + ((size_t)3 << 20) + n0, acc, sm);

    const int t = threadIdx.x, wid = t >> 5, lane = t & 31;
    const int lr = lane >> 2, lc = lane & 3;
    const int wm = (wid & 3) * 64, wn = (wid >> 2) * 64;

    #pragma unroll
    for (int mf = 0; mf < 4; mf++) {
        #pragma unroll
        for (int nf = 0; nf < 8; nf++) {
            int cb = n0 + wn + nf * 8 + 2 * lc;
            float2 bias = *(const float2*)&bo[cb];
            #pragma unroll
            for (int half = 0; half < 2; half++) {
                int m = m0 + wm + mf * 16 + lr + half * 8;
                *(float2*)&out[(size_t)m * DOUT + cb] =
                    make_float2(acc.c[mf][nf][half*2] + bias.x,
                                acc.c[mf][nf][half*2+1] + bias.y);
            }
        }
    }
}

// ---------------------------------------------------------------------------
// Split-KV TF32 flash attention, m32 warp tiles (4 warps / 128 threads).
// Single-buffered K and V with 2-group cp.async rotation:
//   pending invariant at loop top = {K[ch], V[ch]} -> wait_group 1 = K ready,
//   mid-chunk wait_group 0 = V ready. Copies overlap the opposite phase.
// Q lifted once into registers via Ps staging. Partial format unchanged.
// ---------------------------------------------------------------------------
#define KSTR 68
#define VSTR 72
#define PSTR 68
#define ATTN_SMEM ((64*KSTR + 64*VSTR + 128*PSTR) * 4)   // 70656 B

__global__ __launch_bounds__(128, 2) void attn_kernel()
{
    extern __shared__ uint32_t smu[];
    uint32_t* Ks = smu;                   // [64][KSTR]
    uint32_t* Vs = Ks + 64 * KSTR;        // [64][VSTR]
    uint32_t* Ps = Vs + 64 * VSTR;        // [128][PSTR] (Q staging first)

    const int t    = threadIdx.x;
    const int wid  = t >> 5, lane = t & 31;
    const int lr   = lane >> 2, lc = lane & 3;

    const int u    = blockIdx.x;
    const int lvl  = u >> 5, bh = u & 31;
    const int tl   = TL_OF[lvl];
    const int part = PT_OF[lvl];
    const int C    = 2 * tl + 2;
    const int Ah   = tl + 1;
    const int c0   = part ? Ah : 0;
    const int c1   = part ? C  : Ah;
    const int q0   = tl * 128;
    const int ti   = bh * NTILE + tl;

    const float* qbase = g_q + (size_t)(bh * SEQ + q0) * HD;
    const float* kbase = g_k + (size_t)bh * SEQ * HD;
    const float* vbase = g_v + (size_t)bh * SEQ * HD;

    const uint32_t ksm = smem_u32(Ks);
    const uint32_t vsm = smem_u32(Vs);
    const uint32_t psm = smem_u32(Ps);

    // stage Q (group A)
    #pragma unroll
    for (int i = 0; i < 16; i++) {
        int c = t + i * 128;
        int r = c >> 4, sb = c & 15;
        CP16(psm + r * (PSTR*4) + sb * 16, qbase + (size_t)r * HD + sb * 4);
    }
    CP_COMMIT();
    // K chunk c0 (group B)
    {
        const float* kp = kbase + (size_t)c0 * 64 * HD;
        #pragma unroll
        for (int i = 0; i < 8; i++) {
            int c = t + i * 128;
            int r = c >> 4, sb = c & 15;
            CP16(ksm + r * (KSTR*4) + sb * 16, kp + (size_t)r * HD + sb * 4);
        }
        CP_COMMIT();
    }
    // V chunk c0 (group C)
    {
        const float* vp = vbase + (size_t)c0 * 64 * HD;
        #pragma unroll
        for (int i = 0; i < 8; i++) {
            int c = t + i * 128;
            int r = c >> 4, sb = c & 15;
            CP16(vsm + r * (VSTR*4) + sb * 16, vp + (size_t)r * HD + sb * 4);
        }
        CP_COMMIT();
    }

    CP_WAIT2();          // Q staged
    __syncthreads();

    // lift Q fragments (m32 per warp); Ps rows [32w,32w+32) are warp-private
    uint32_t qa[8][8];
    {
        const int r = 32 * wid + lr;
        #pragma unroll
        for (int ks = 0; ks < 8; ks++) {
            const int d0 = ks * 8;
            qa[ks][0] = Ps[r * PSTR + d0 + lc];
            qa[ks][1] = Ps[(r + 8) * PSTR + d0 + lc];
            qa[ks][2] = Ps[r * PSTR + d0 + lc + 4];
            qa[ks][3] = Ps[(r + 8) * PSTR + d0 + lc + 4];
            qa[ks][4] = Ps[(r + 16) * PSTR + d0 + lc];
            qa[ks][5] = Ps[(r + 24) * PSTR + d0 + lc];
            qa[ks][6] = Ps[(r + 16) * PSTR + d0 + lc + 4];
            qa[ks][7] = Ps[(r + 24) * PSTR + d0 + lc + 4];
        }
    }

    float mrow[4], lsum[4];
    #pragma unroll
    for (int i = 0; i < 4; i++) { mrow[i] = -1e30f; lsum[i] = 0.f; }
    float o[2][8][4];
    #pragma unroll
    for (int mf = 0; mf < 2; mf++)
        #pragma unroll
        for (int nf = 0; nf < 8; nf++)
            #pragma unroll
            for (int r = 0; r < 4; r++) o[mf][nf][r] = 0.f;

    for (int ch = c0; ch < c1; ch++) {
        const int kb = ch * 64;
        CP_WAIT1();          // K[ch] arrived (V[ch] may still be in flight)
        __syncthreads();     // K visible to all; prev-V readers drained earlier

        // ---- S = Q K^T : warp's 32 rows x 64 keys ----
        float s[2][8][4];
        #pragma unroll
        for (int mf = 0; mf < 2; mf++)
            #pragma unroll
            for (int nf = 0; nf < 8; nf++)
                #pragma unroll
                for (int r = 0; r < 4; r++) s[mf][nf][r] = 0.f;

        #pragma unroll
        for (int ks = 0; ks < 8; ks++) {
            const int d0 = ks * 8;
            #pragma unroll
            for (int nf = 0; nf < 8; nf++) {
                uint32_t b0 = Ks[(nf * 8 + lr) * KSTR + d0 + lc];
                uint32_t b1 = Ks[(nf * 8 + lr) * KSTR + d0 + lc + 4];
                mma_tf32(s[0][nf][0], s[0][nf][1], s[0][nf][2], s[0][nf][3],
                         qa[ks][0], qa[ks][1], qa[ks][2], qa[ks][3], b0, b1);
                mma_tf32(s[1][nf][0], s[1][nf][1], s[1][nf][2], s[1][nf][3],
                         qa[ks][4], qa[ks][5], qa[ks][6], qa[ks][7], b0, b1);
            }
        }

        CP_WAIT0();          // V[ch] arrived
        __syncthreads();     // all warps done reading K[ch]; V visible
        if (ch + 1 < c1) {   // refill K for next chunk (overlaps softmax+PV)
            const float* kp = kbase + (size_t)(kb + 64) * HD;
            #pragma unroll
            for (int i = 0; i < 8; i++) {
                int c = t + i * 128;
                int r = c >> 4, sb = c & 15;
                CP16(ksm + r * (KSTR*4) + sb * 16, kp + (size_t)r * HD + sb * 4);
            }
            CP_COMMIT();
        }

        // ---- causal mask (diagonal chunks only) ----
        if (kb >= q0) {
            const int rb = q0 + 32 * wid + lr;
            #pragma unroll
            for (int mf = 0; mf < 2; mf++) {
                int r0 = rb + mf * 16, r1 = r0 + 8;
                #pragma unroll
                for (int nf = 0; nf < 8; nf++) {
                    int cc0 = kb + nf * 8 + 2 * lc, cc1 = cc0 + 1;
                    if (cc0 > r0) s[mf][nf][0] = -1e30f;
                    if (cc1 > r0) s[mf][nf][1] = -1e30f;
                    if (cc0 > r1) s[mf][nf][2] = -1e30f;
                    if (cc1 > r1) s[mf][nf][3] = -1e30f;
                }
            }
        }

        // ---- online softmax: 4 row-slots (mf, half) ----
        float mx[4];
        #pragma unroll
        for (int i = 0; i < 4; i++) mx[i] = -1e30f;
        #pragma unroll
        for (int mf = 0; mf < 2; mf++)
            #pragma unroll
            for (int nf = 0; nf < 8; nf++) {
                mx[2*mf]   = fmaxf(mx[2*mf],   fmaxf(s[mf][nf][0], s[mf][nf][1]));
                mx[2*mf+1] = fmaxf(mx[2*mf+1], fmaxf(s[mf][nf][2], s[mf][nf][3]));
            }
        #pragma unroll
        for (int off = 1; off < 4; off <<= 1)
            #pragma unroll
            for (int i = 0; i < 4; i++)
                mx[i] = fmaxf(mx[i], __shfl_xor_sync(0xffffffffu, mx[i], off));

        float mn[4], sc[4], rs[4];
        #pragma unroll
        for (int i = 0; i < 4; i++) {
            mn[i] = fmaxf(mrow[i], mx[i]);
            sc[i] = exp2f(mrow[i] - mn[i]);
            mrow[i] = mn[i];
            rs[i] = 0.f;
        }

        const int prow = (32 * wid + lr) * PSTR;
        #pragma unroll
        for (int mf = 0; mf < 2; mf++) {
            #pragma unroll
            for (int nf = 0; nf < 8; nf++) {
                float p0 = exp2f(s[mf][nf][0] - mn[2*mf]);
                float p1 = exp2f(s[mf][nf][1] - mn[2*mf]);
                float p2 = exp2f(s[mf][nf][2] - mn[2*mf+1]);
                float p3 = exp2f(s[mf][nf][3] - mn[2*mf+1]);
                rs[2*mf]   += p0 + p1;
                rs[2*mf+1] += p2 + p3;
                int cofs = nf * 8 + 2 * lc;
                *(uint2*)&Ps[prow + mf * 16 * PSTR + cofs] =
                    make_uint2(f2tf(p0), f2tf(p1));
                *(uint2*)&Ps[prow + (mf * 16 + 8) * PSTR + cofs] =
                    make_uint2(f2tf(p2), f2tf(p3));
                o[mf][nf][0] *= sc[2*mf];   o[mf][nf][1] *= sc[2*mf];
                o[mf][nf][2] *= sc[2*mf+1]; o[mf][nf][3] *= sc[2*mf+1];
            }
        }
        #pragma unroll
        for (int off = 1; off < 4; off <<= 1)
            #pragma unroll
            for (int i = 0; i < 4; i++)
                rs[i] += __shfl_xor_sync(0xffffffffu, rs[i], off);
        #pragma unroll
        for (int i = 0; i < 4; i++) lsum[i] = lsum[i] * sc[i] + rs[i];

        __syncwarp();   // P rows are warp-private

        // ---- O += P @ V ----
        #pragma unroll
        for (int ks = 0; ks < 8; ks++) {
            const int k0 = ks * 8;
            const int r = 32 * wid + lr;
            uint32_t a0 = Ps[r * PSTR + k0 + lc];
            uint32_t a1 = Ps[(r + 8) * PSTR + k0 + lc];
            uint32_t a2 = Ps[r * PSTR + k0 + lc + 4];
            uint32_t a3 = Ps[(r + 8) * PSTR + k0 + lc + 4];
            uint32_t a4 = Ps[(r + 16) * PSTR + k0 + lc];
            uint32_t a5 = Ps[(r + 24) * PSTR + k0 + lc];
            uint32_t a6 = Ps[(r + 16) * PSTR + k0 + lc + 4];
            uint32_t a7 = Ps[(r + 24) * PSTR + k0 + lc + 4];
            #pragma unroll
            for (int nf = 0; nf < 8; nf++) {
                uint32_t b0 = Vs[(k0 + lc) * VSTR + nf * 8 + lr];
                uint32_t b1 = Vs[(k0 + lc + 4) * VSTR + nf * 8 + lr];
                mma_tf32(o[0][nf][0], o[0][nf][1], o[0][nf][2], o[0][nf][3],
                         a0, a1, a2, a3, b0, b1);
                mma_tf32(o[1][nf][0], o[1][nf][1], o[1][nf][2], o[1][nf][3],
                         a4, a5, a6, a7, b0, b1);
            }
        }

        __syncthreads();     // all warps done reading V[ch]
        if (ch + 1 < c1) {   // refill V for next chunk (overlaps next S)
            const float* vp = vbase + (size_t)(kb + 64) * HD;
            #pragma unroll
            for (int i = 0; i < 8; i++) {
                int c = t + i * 128;
                int r = c >> 4, sb = c & 15;
                CP16(vsm + r * (VSTR*4) + sb * 16, vp + (size_t)r * HD + sb * 4);
            }
            CP_COMMIT();
        }
    }

    // write partials (unnormalized o; per-row m, l)
    float* po = g_po[part];
    const int rb = 32 * wid + lr;
    #pragma unroll
    for (int mf = 0; mf < 2; mf++) {
        int r0 = rb + mf * 16, r1 = r0 + 8;
        #pragma unroll
        for (int nf = 0; nf < 8; nf++) {
            int cb = nf * 8 + 2 * lc;
            *(float2*)&po[((size_t)ti * 128 + r0) * 64 + cb] =
                make_float2(o[mf][nf][0], o[mf][nf][1]);
            *(float2*)&po[((size_t)ti * 128 + r1) * 64 + cb] =
                make_float2(o[mf][nf][2], o[mf][nf][3]);
        }
        if (lc == 0) {
            g_pm[part][ti * 128 + r0] = mrow[2*mf];
            g_pm[part][ti * 128 + r1] = mrow[2*mf+1];
            g_pl[part][ti * 128 + r0] = lsum[2*mf];
            g_pl[part][ti * 128 + r1] = lsum[2*mf+1];
        }
    }
}

// ---------------------------------------------------------------------------
// Merge partials -> g_ctx (tf32-rounded). grid 512, block 256.
// ---------------------------------------------------------------------------
__global__ __launch_bounds__(256) void merge_attn()
{
    const int ti = blockIdx.x, t = threadIdx.x;
    const int r = t >> 1, hh = t & 1;
    const int bh = ti >> 4, tl = ti & 15;
    const int b = bh >> 4, h = bh & 15;
    const int grow = tl * 128 + r;

    const int ri = ti * 128 + r;
    float ma = g_pm[0][ri], mb = g_pm[1][ri];
    float la = g_pl[0][ri], lb = g_pl[1][ri];
    float M  = fmaxf(ma, mb);
    float wa = exp2f(ma - M), wb = exp2f(mb - M);
    float inv = 1.f / (la * wa + lb * wb);
    wa *= inv; wb *= inv;

    const float4* pa = (const float4*)&g_po[0][((size_t)ri) * 64 + hh * 32];
    const float4* pb = (const float4*)&g_po[1][((size_t)ri) * 64 + hh * 32];
    uint4* dst = (uint4*)&g_ctx[(size_t)(b * SEQ + grow) * DOUT + h * HD + hh * 32];

    #pragma unroll
    for (int i = 0; i < 8; i++) {
        float4 va = pa[i], vb = pb[i];
        dst[i] = make_uint4(f2tf(va.x * wa + vb.x * wb),
                            f2tf(va.y * wa + vb.y * wb),
                            f2tf(va.z * wa + vb.z * wb),
                            f2tf(va.w * wa + vb.w * wb));
    }
}

// ---------------------------------------------------------------------------
extern "C" void kernel_launch(void* const* d_in, const int* in_sizes, int n_in,
                              void* d_out, int out_size)
{
    const float* x  = (const float*)d_in[0];
    const float* Wq = (const float*)d_in[1];
    const float* Wk = (const float*)d_in[2];
    const float* Wv = (const float*)d_in[3];
    const float* Wo = (const float*)d_in[4];
    const float* bo = (const float*)d_in[5];
    float* out = (float*)d_out;

    cudaFuncSetAttribute(attn_kernel,
                         cudaFuncAttributeMaxDynamicSharedMemorySize, ATTN_SMEM);
    cudaFuncSetAttribute(qkv_gemm,
                         cudaFuncAttributeMaxDynamicSharedMemorySize, GEMM_SMEM);
    cudaFuncSetAttribute(proj_gemm,
                         cudaFuncAttributeMaxDynamicSharedMemorySize, GEMM_SMEM);

    round_w<<<dim3(1024, 4), 256>>>(Wq, Wk, Wv, Wo);
    round_x<<<4096, 256>>>(x);
    qkv_gemm<<<dim3(DOUT / 128, MROWS / 256, 3), 256, GEMM_SMEM>>>();
    attn_kernel<<<1024, 128, ATTN_SMEM>>>();
    merge_attn<<<NTI, 256>>>();
    proj_gemm<<<dim3(DOUT / 128, MROWS / 256), 256, GEMM_SMEM>>>(bo, out);
}